// round 1
// baseline (speedup 1.0000x reference)
#include <cuda_runtime.h>
#include <math.h>

#define NN 16384
#define EE 131072
#define GG 32

// ---------------- scratch (static __device__, no allocations) ----------------
__device__ int   g_indeg[NN];
__device__ int   g_rowptr[NN + 1];
__device__ int   g_rowcur[NN];
__device__ int   g_srcs[EE];
__device__ float g_dis[NN];

__device__ float g_agg0[NN * 5];
__device__ float g_h1raw[NN * 64];
__device__ float g_h1[NN * 64];
__device__ float g_sageagg[NN * 64];
__device__ float g_h2raw[NN * 128];
__device__ float g_h2[NN * 128];
__device__ float g_vsrc[512];
__device__ float g_vdst[512];
__device__ float g_es[NN * 4];
__device__ float g_ed[NN * 4];
__device__ float g_gatagg[NN * 512];
__device__ float g_h3raw[NN * 256];
__device__ float g_h3[NN * 256];
__device__ float g_gcn4agg[NN * 256];
__device__ float g_h4raw[NN * 512];
__device__ float g_h4[NN * 512];

__device__ float g_bnps[128 * 512];
__device__ float g_bnpq[128 * 512];
__device__ float g_mu[512];
__device__ float g_rstd[512];

__device__ int   g_gcnt[GG];
__device__ float g_pooled[GG * 1024];

// ---------------- graph preprocessing ----------------
__global__ void init_kernel() {
    int i = blockIdx.x * blockDim.x + threadIdx.x;
    if (i < NN) g_indeg[i] = 0;
    if (i < GG) g_gcnt[i] = 0;
}

__global__ void count_deg_kernel(const int* __restrict__ dst) {
    int e = blockIdx.x * blockDim.x + threadIdx.x;
    if (e < EE) atomicAdd(&g_indeg[dst[e]], 1);
}

__global__ void scan_kernel() {
    __shared__ int part[1024];
    int t = threadIdx.x;
    int base = t * 16;
    int loc[16];
    int s = 0;
#pragma unroll
    for (int i = 0; i < 16; i++) { loc[i] = s; s += g_indeg[base + i]; }
    part[t] = s;
    __syncthreads();
    for (int off = 1; off < 1024; off <<= 1) {
        int v = (t >= off) ? part[t - off] : 0;
        __syncthreads();
        part[t] += v;
        __syncthreads();
    }
    int pre = (t > 0) ? part[t - 1] : 0;
#pragma unroll
    for (int i = 0; i < 16; i++) {
        g_rowptr[base + i] = pre + loc[i];
        g_rowcur[base + i] = pre + loc[i];
    }
    if (t == 1023) g_rowptr[NN] = part[1023];
}

__global__ void dis_kernel() {
    int i = blockIdx.x * blockDim.x + threadIdx.x;
    if (i < NN) g_dis[i] = rsqrtf((float)(g_indeg[i] + 1));
}

__global__ void scatter_kernel(const int* __restrict__ src, const int* __restrict__ dst) {
    int e = blockIdx.x * blockDim.x + threadIdx.x;
    if (e < EE) {
        int p = atomicAdd(&g_rowcur[dst[e]], 1);
        g_srcs[p] = src[e];
    }
}

// deterministic: sort each node's src list (insertion sort, small degree)
__global__ void sort_kernel() {
    int d = blockIdx.x * blockDim.x + threadIdx.x;
    if (d >= NN) return;
    int s = g_rowptr[d], e = g_rowptr[d + 1];
    for (int i = s + 1; i < e; i++) {
        int v = g_srcs[i];
        int j = i - 1;
        while (j >= s && g_srcs[j] > v) { g_srcs[j + 1] = g_srcs[j]; j--; }
        g_srcs[j + 1] = v;
    }
}

// ---------------- aggregation (CSR, one block per dst) ----------------
// SAGE=false: GCN norm (self loop dis[d]^2, edges dis[s]*dis[d])
// SAGE=true:  mean of src features (no self loop)
template <int C, int TPB, bool SAGE>
__global__ void agg_kernel(const float* __restrict__ feat, float* __restrict__ out) {
    constexpr int NPC = (C + TPB - 1) / TPB;
    int d = blockIdx.x;
    int t = threadIdx.x;
    int start = g_rowptr[d], end = g_rowptr[d + 1];
    float acc[NPC];
    if (!SAGE) {
        float dd = g_dis[d];
#pragma unroll
        for (int i = 0; i < NPC; i++) {
            int c = t + i * TPB;
            acc[i] = (c < C) ? dd * dd * feat[(size_t)d * C + c] : 0.f;
        }
        for (int p = start; p < end; p++) {
            int s = g_srcs[p];
            float w = g_dis[s] * dd;
#pragma unroll
            for (int i = 0; i < NPC; i++) {
                int c = t + i * TPB;
                if (c < C) acc[i] += w * feat[(size_t)s * C + c];
            }
        }
    } else {
#pragma unroll
        for (int i = 0; i < NPC; i++) acc[i] = 0.f;
        for (int p = start; p < end; p++) {
            int s = g_srcs[p];
#pragma unroll
            for (int i = 0; i < NPC; i++) {
                int c = t + i * TPB;
                if (c < C) acc[i] += feat[(size_t)s * C + c];
            }
        }
        float inv = 1.f / fmaxf((float)(end - start), 1.f);
#pragma unroll
        for (int i = 0; i < NPC; i++) acc[i] *= inv;
    }
#pragma unroll
    for (int i = 0; i < NPC; i++) {
        int c = t + i * TPB;
        if (c < C) out[(size_t)d * C + c] = acc[i];
    }
}

// ---------------- GEMMs ----------------
__global__ void gemm_k5(const float* __restrict__ A, const float* __restrict__ B,
                        float* __restrict__ C) {
    int idx = blockIdx.x * blockDim.x + threadIdx.x;  // NN*64
    int n = idx >> 6, j = idx & 63;
    const float* a = A + n * 5;
    float acc = a[0] * B[j] + a[1] * B[64 + j] + a[2] * B[128 + j] +
                a[3] * B[192 + j] + a[4] * B[256 + j];
    C[idx] = acc;
}

// C[M,Nc] (+)= A[M,K] @ B[K,Nc]; M%128==0, Nc%128==0, K%16==0; pointers 16B-aligned
template <bool ACCUM>
__global__ __launch_bounds__(256) void gemm_kernel(
    const float* __restrict__ A, int lda,
    const float* __restrict__ B, int ldb,
    float* __restrict__ C, int ldc,
    int M, int Nc, int K) {
    __shared__ float As[16][132];
    __shared__ float Bs[16][128];
    int tid = threadIdx.x;
    int bm = blockIdx.y * 128;
    int bn = blockIdx.x * 128;
    int tr = tid / 16, tc = tid % 16;
    int arow = tid >> 2;
    int ac4 = (tid & 3) * 4;
    int brow = tid >> 5;
    int bc4 = (tid & 31) * 4;
    float acc[8][8];
#pragma unroll
    for (int i = 0; i < 8; i++)
#pragma unroll
        for (int j = 0; j < 8; j++) acc[i][j] = 0.f;

    for (int kt = 0; kt < K; kt += 16) {
#pragma unroll
        for (int p = 0; p < 2; p++) {
            int r = arow + p * 64;
            float4 a = *reinterpret_cast<const float4*>(A + (size_t)(bm + r) * lda + kt + ac4);
            As[ac4 + 0][r] = a.x; As[ac4 + 1][r] = a.y;
            As[ac4 + 2][r] = a.z; As[ac4 + 3][r] = a.w;
        }
#pragma unroll
        for (int p = 0; p < 2; p++) {
            int r = brow + p * 8;
            float4 b = *reinterpret_cast<const float4*>(B + (size_t)(kt + r) * ldb + bn + bc4);
            *reinterpret_cast<float4*>(&Bs[r][bc4]) = b;
        }
        __syncthreads();
#pragma unroll
        for (int kk = 0; kk < 16; kk++) {
            float af[8], bf[8];
#pragma unroll
            for (int i = 0; i < 8; i++) af[i] = As[kk][tr * 8 + i];
#pragma unroll
            for (int i = 0; i < 8; i++) bf[i] = Bs[kk][tc * 8 + i];
#pragma unroll
            for (int i = 0; i < 8; i++)
#pragma unroll
                for (int j = 0; j < 8; j++) acc[i][j] += af[i] * bf[j];
        }
        __syncthreads();
    }
#pragma unroll
    for (int i = 0; i < 8; i++) {
        size_t r = (size_t)(bm + tr * 8 + i) * ldc + bn + tc * 8;
#pragma unroll
        for (int j = 0; j < 8; j += 4) {
            float4* cp = reinterpret_cast<float4*>(C + r + j);
            float4 v;
            v.x = acc[i][j + 0]; v.y = acc[i][j + 1];
            v.z = acc[i][j + 2]; v.w = acc[i][j + 3];
            if (ACCUM) {
                float4 o = *cp;
                v.x += o.x; v.y += o.y; v.z += o.z; v.w += o.w;
            }
            *cp = v;
        }
    }
}

// ---------------- batchnorm (deterministic two-level reduction) ----------------
__global__ void bn_stats(const float* __restrict__ x, int C) {
    int tid = threadIdx.x;
    int cw = C < 256 ? C : 256;
    int groups = 256 / cw;
    int lc = tid % cw, grp = tid / cw;
    int rpb = NN / 128;
    int r0 = blockIdx.x * rpb;
    float s0 = 0, q0 = 0, s1 = 0, q1 = 0;
    for (int r = r0 + grp; r < r0 + rpb; r += groups) {
        float v = x[(size_t)r * C + lc];
        s0 += v; q0 += v * v;
        if (C == 512) {
            float w = x[(size_t)r * C + lc + 256];
            s1 += w; q1 += w * w;
        }
    }
    __shared__ float ss[256], sq[256];
    ss[tid] = s0; sq[tid] = q0;
    __syncthreads();
    if (grp == 0) {
        for (int g2 = 1; g2 < groups; g2++) { s0 += ss[g2 * cw + lc]; q0 += sq[g2 * cw + lc]; }
        g_bnps[blockIdx.x * 512 + lc] = s0;
        g_bnpq[blockIdx.x * 512 + lc] = q0;
        if (C == 512) {
            g_bnps[blockIdx.x * 512 + lc + 256] = s1;
            g_bnpq[blockIdx.x * 512 + lc + 256] = q1;
        }
    }
}

__global__ void bn_finalize(int C) {
    int c = blockIdx.x * blockDim.x + threadIdx.x;
    if (c >= C) return;
    float s = 0, q = 0;
    for (int b = 0; b < 128; b++) { s += g_bnps[b * 512 + c]; q += g_bnpq[b * 512 + c]; }
    float mu = s * (1.f / NN);
    float var = q * (1.f / NN) - mu * mu;
    g_mu[c] = mu;
    g_rstd[c] = rsqrtf(var + 1e-5f);
}

__global__ void bn_apply(const float* __restrict__ x, float* __restrict__ y,
                         const float* __restrict__ g, const float* __restrict__ b,
                         int Cm1, int total) {
    int idx = blockIdx.x * blockDim.x + threadIdx.x;
    if (idx >= total) return;
    int c = idx & Cm1;
    y[idx] = fmaxf(0.f, (x[idx] - g_mu[c]) * g_rstd[c] * g[c] + b[c]);
}

// ---------------- GAT ----------------
__global__ void vsd_kernel(const float* __restrict__ W, const float* __restrict__ asrc,
                           const float* __restrict__ adst) {
    int idx = blockIdx.x * blockDim.x + threadIdx.x;
    if (idx >= 512) return;
    int h = idx >> 7, k = idx & 127;
    float a = 0, b = 0;
    const float* wr = W + (size_t)k * 1024 + h * 256;
    const float* as = asrc + h * 256;
    const float* ad = adst + h * 256;
    for (int j = 0; j < 256; j++) { float w = wr[j]; a += w * as[j]; b += w * ad[j]; }
    g_vsrc[idx] = a;
    g_vdst[idx] = b;
}

__global__ void esed_kernel(const float* __restrict__ h2) {
    int idx = blockIdx.x * blockDim.x + threadIdx.x;
    if (idx >= NN * 4) return;
    int n = idx >> 2, h = idx & 3;
    const float* r = h2 + (size_t)n * 128;
    const float* vs = g_vsrc + h * 128;
    const float* vd = g_vdst + h * 128;
    float a = 0, b = 0;
#pragma unroll 8
    for (int k = 0; k < 128; k++) { float x = r[k]; a += x * vs[k]; b += x * vd[k]; }
    g_es[idx] = a;
    g_ed[idx] = b;
}

__device__ __forceinline__ float lrelu(float x) { return x > 0.f ? x : 0.2f * x; }

__global__ void gat_agg_kernel(const float* __restrict__ h2) {
    int d = blockIdx.x;
    int t = threadIdx.x;  // 128
    int start = g_rowptr[d], end = g_rowptr[d + 1];
    float edv[4], esd[4], m[4];
#pragma unroll
    for (int h = 0; h < 4; h++) {
        edv[h] = g_ed[d * 4 + h];
        esd[h] = g_es[d * 4 + h];
        m[h] = lrelu(esd[h] + edv[h]);  // self loop
    }
    for (int p = start; p < end; p++) {
        int s = g_srcs[p];
#pragma unroll
        for (int h = 0; h < 4; h++) m[h] = fmaxf(m[h], lrelu(g_es[s * 4 + h] + edv[h]));
    }
    float z[4], acc[4];
    float hv = h2[(size_t)d * 128 + t];
#pragma unroll
    for (int h = 0; h < 4; h++) {
        float ex = expf(lrelu(esd[h] + edv[h]) - m[h]);
        z[h] = ex;
        acc[h] = ex * hv;
    }
    for (int p = start; p < end; p++) {
        int s = g_srcs[p];
        float sv = h2[(size_t)s * 128 + t];
#pragma unroll
        for (int h = 0; h < 4; h++) {
            float ex = expf(lrelu(g_es[s * 4 + h] + edv[h]) - m[h]);
            z[h] += ex;
            acc[h] += ex * sv;
        }
    }
#pragma unroll
    for (int h = 0; h < 4; h++)
        g_gatagg[(size_t)d * 512 + h * 128 + t] = acc[h] / z[h];
}

// ---------------- pooling + FC ----------------
__global__ void count_batch_kernel(const int* __restrict__ batch) {
    int i = blockIdx.x * blockDim.x + threadIdx.x;
    if (i < NN) atomicAdd(&g_gcnt[batch[i]], 1);
}

__global__ void pool_kernel() {
    int g = blockIdx.x, c = threadIdx.x;  // 32 blocks x 512 threads
    int start = 0;
    for (int i = 0; i < g; i++) start += g_gcnt[i];
    int cnt = g_gcnt[g];
    float s = 0.f, mx = -3.402823e38f;
    for (int r = start; r < start + cnt; r++) {
        float v = g_h4[(size_t)r * 512 + c];
        s += v;
        mx = fmaxf(mx, v);
    }
    g_pooled[g * 1024 + c] = s / fmaxf((float)cnt, 1.f);
    g_pooled[g * 1024 + 512 + c] = (cnt > 0) ? mx : 0.f;
}

__global__ void fc_kernel(const float* __restrict__ w, const float* __restrict__ bias,
                          float* __restrict__ out) {
    __shared__ float pt[32 * 128];
    int jb = blockIdx.x * 32;
    int j = jb + (threadIdx.x & 31);
    int gq = threadIdx.x >> 5;  // 0..7 -> 4 graphs each
    float acc[4] = {0, 0, 0, 0};
    for (int kt = 0; kt < 1024; kt += 128) {
        __syncthreads();
        for (int i = threadIdx.x; i < 4096; i += 256) {
            int g = i >> 7, kk = i & 127;
            pt[g * 128 + kk] = g_pooled[g * 1024 + kt + kk];
        }
        __syncthreads();
        for (int kk = 0; kk < 128; kk++) {
            float wv = w[(size_t)(kt + kk) * 1024 + j];
#pragma unroll
            for (int i = 0; i < 4; i++) acc[i] += pt[(gq * 4 + i) * 128 + kk] * wv;
        }
    }
#pragma unroll
    for (int i = 0; i < 4; i++) out[(gq * 4 + i) * 1024 + j] = acc[i] + bias[j];
}

// ---------------- driver ----------------
extern "C" void kernel_launch(void* const* d_in, const int* in_sizes, int n_in,
                              void* d_out, int out_size) {
    const float* x        = (const float*)d_in[0];
    const int*   eidx     = (const int*)d_in[1];
    const int*   batch    = (const int*)d_in[2];
    const float* gcn1_w   = (const float*)d_in[3];
    const float* sage_wl  = (const float*)d_in[5];
    const float* sage_wr  = (const float*)d_in[6];
    const float* gat_w    = (const float*)d_in[8];
    const float* gat_asrc = (const float*)d_in[9];
    const float* gat_adst = (const float*)d_in[10];
    const float* gcn4_w   = (const float*)d_in[12];
    const float* bn1_g = (const float*)d_in[14], *bn1_b = (const float*)d_in[15];
    const float* bn2_g = (const float*)d_in[16], *bn2_b = (const float*)d_in[17];
    const float* bn3_g = (const float*)d_in[18], *bn3_b = (const float*)d_in[19];
    const float* bn4_g = (const float*)d_in[20], *bn4_b = (const float*)d_in[21];
    const float* fc_w = (const float*)d_in[22], *fc_b = (const float*)d_in[23];
    const int* src = eidx;
    const int* dst = eidx + EE;
    float* out = (float*)d_out;

    float *h1raw, *h1, *sageagg, *h2raw, *h2, *gatagg, *h3raw, *h3, *gcn4agg, *h4raw, *h4, *agg0;
    // device symbols are directly referenced inside kernels; get raw ptrs for the generic GEMM
    cudaGetSymbolAddress((void**)&agg0, g_agg0);
    cudaGetSymbolAddress((void**)&h1raw, g_h1raw);
    cudaGetSymbolAddress((void**)&h1, g_h1);
    cudaGetSymbolAddress((void**)&sageagg, g_sageagg);
    cudaGetSymbolAddress((void**)&h2raw, g_h2raw);
    cudaGetSymbolAddress((void**)&h2, g_h2);
    cudaGetSymbolAddress((void**)&gatagg, g_gatagg);
    cudaGetSymbolAddress((void**)&h3raw, g_h3raw);
    cudaGetSymbolAddress((void**)&h3, g_h3);
    cudaGetSymbolAddress((void**)&gcn4agg, g_gcn4agg);
    cudaGetSymbolAddress((void**)&h4raw, g_h4raw);
    cudaGetSymbolAddress((void**)&h4, g_h4);

    // graph preprocessing
    init_kernel<<<64, 256>>>();
    count_deg_kernel<<<EE / 256, 256>>>(dst);
    scan_kernel<<<1, 1024>>>();
    dis_kernel<<<64, 256>>>();
    scatter_kernel<<<EE / 256, 256>>>(src, dst);
    sort_kernel<<<64, 256>>>();

    // layer 1: GCN(5->64) : aggregate x, then small GEMM, bn+relu
    agg_kernel<5, 32, false><<<NN, 32>>>(x, agg0);
    gemm_k5<<<NN * 64 / 256, 256>>>(agg0, gcn1_w, h1raw);
    bn_stats<<<128, 256>>>(h1raw, 64);
    bn_finalize<<<1, 64>>>(64);
    bn_apply<<<NN * 64 / 256, 256>>>(h1raw, h1, bn1_g, bn1_b, 63, NN * 64);

    // layer 2: SAGE(64->128)
    agg_kernel<64, 64, true><<<NN, 64>>>(h1, sageagg);
    gemm_kernel<false><<<dim3(1, 128), 256>>>(sageagg, 64, sage_wl, 128, h2raw, 128, NN, 128, 64);
    gemm_kernel<true><<<dim3(1, 128), 256>>>(h1, 64, sage_wr, 128, h2raw, 128, NN, 128, 64);
    bn_stats<<<128, 256>>>(h2raw, 128);
    bn_finalize<<<1, 128>>>(128);
    bn_apply<<<NN * 128 / 256, 256>>>(h2raw, h2, bn2_g, bn2_b, 127, NN * 128);

    // layer 3: GAT(128->256, 4 heads). Aggregate h2 with attention, THEN multiply.
    vsd_kernel<<<2, 256>>>(gat_w, gat_asrc, gat_adst);
    esed_kernel<<<NN * 4 / 256, 256>>>(h2);
    gat_agg_kernel<<<NN, 128>>>(h2);
    gemm_kernel<false><<<dim3(2, 128), 256>>>(gatagg + 0 * 128, 512, gat_w + 0 * 256, 1024,
                                              h3raw, 256, NN, 256, 128);
    gemm_kernel<true><<<dim3(2, 128), 256>>>(gatagg + 1 * 128, 512, gat_w + 1 * 256, 1024,
                                             h3raw, 256, NN, 256, 128);
    gemm_kernel<true><<<dim3(2, 128), 256>>>(gatagg + 2 * 128, 512, gat_w + 2 * 256, 1024,
                                             h3raw, 256, NN, 256, 128);
    gemm_kernel<true><<<dim3(2, 128), 256>>>(gatagg + 3 * 128, 512, gat_w + 3 * 256, 1024,
                                             h3raw, 256, NN, 256, 128);
    bn_stats<<<128, 256>>>(h3raw, 256);
    bn_finalize<<<1, 256>>>(256);
    bn_apply<<<NN * 256 / 256, 256>>>(h3raw, h3, bn3_g, bn3_b, 255, NN * 256);

    // layer 4: GCN(256->512): aggregate h3, then GEMM
    agg_kernel<256, 256, false><<<NN, 256>>>(h3, gcn4agg);
    gemm_kernel<false><<<dim3(4, 128), 256>>>(gcn4agg, 256, gcn4_w, 512, h4raw, 512, NN, 512, 256);
    bn_stats<<<128, 256>>>(h4raw, 512);
    bn_finalize<<<2, 256>>>(512);
    bn_apply<<<NN * 512 / 256, 256>>>(h4raw, h4, bn4_g, bn4_b, 511, NN * 512);

    // pooling + FC
    count_batch_kernel<<<64, 256>>>(batch);
    pool_kernel<<<GG, 512>>>();
    fc_kernel<<<32, 256>>>(fc_w, fc_b, out);
}

// round 3
// speedup vs baseline: 1.1370x; 1.1370x over previous
#include <cuda_runtime.h>
#include <math.h>

#define NN 16384
#define EE 131072
#define GG 32

// ---------------- scratch (static __device__, no allocations) ----------------
__device__ int   g_indeg[NN];
__device__ int   g_rowptr[NN + 1];
__device__ int   g_rowcur[NN];
__device__ int   g_srcs[EE];
__device__ float g_dis[NN];

__device__ float g_agg0[NN * 5];
__device__ float g_h1raw[NN * 64];
__device__ float g_cat2[NN * 128];      // [:,0:64)=sage agg, [:,64:128)=h1
__device__ float g_h2raw[NN * 128];
__device__ float g_h2[NN * 128];
__device__ float g_vsrc[512];
__device__ float g_vdst[512];
__device__ float g_es[NN * 4];
__device__ float g_ed[NN * 4];
__device__ float g_gatagg[NN * 512];
__device__ float g_h3raw[NN * 256];
__device__ float g_h3[NN * 256];
__device__ float g_gcn4agg[NN * 256];
__device__ float g_h4raw[NN * 512];
__device__ float g_h4[NN * 512];

__device__ float g_Bsage[128 * 128];    // [wl;wr] stacked
__device__ float g_Bgat[512 * 256];     // head-stacked gat_w

__device__ float g_bnps[128 * 512];
__device__ float g_bnpq[128 * 512];
__device__ float g_mu[512];
__device__ float g_rstd[512];

__device__ int   g_gcnt[GG];
__device__ float g_pooled[GG * 1024];

// ---------------- graph preprocessing ----------------
__global__ void init_kernel() {
    int i = blockIdx.x * blockDim.x + threadIdx.x;
    if (i < NN) g_indeg[i] = 0;
    if (i < GG) g_gcnt[i] = 0;
}

__global__ void count_deg_kernel(const int* __restrict__ dst) {
    int e = blockIdx.x * blockDim.x + threadIdx.x;
    if (e < EE) atomicAdd(&g_indeg[dst[e]], 1);
}

__global__ void scan_kernel() {
    __shared__ int part[1024];
    int t = threadIdx.x;
    int base = t * 16;
    int loc[16];
    int s = 0;
#pragma unroll
    for (int i = 0; i < 16; i++) { loc[i] = s; s += g_indeg[base + i]; }
    part[t] = s;
    __syncthreads();
    for (int off = 1; off < 1024; off <<= 1) {
        int v = (t >= off) ? part[t - off] : 0;
        __syncthreads();
        part[t] += v;
        __syncthreads();
    }
    int pre = (t > 0) ? part[t - 1] : 0;
#pragma unroll
    for (int i = 0; i < 16; i++) {
        g_rowptr[base + i] = pre + loc[i];
        g_rowcur[base + i] = pre + loc[i];
    }
    if (t == 1023) g_rowptr[NN] = part[1023];
}

__global__ void dis_kernel() {
    int i = blockIdx.x * blockDim.x + threadIdx.x;
    if (i < NN) g_dis[i] = rsqrtf((float)(g_indeg[i] + 1));
}

__global__ void scatter_kernel(const int* __restrict__ src, const int* __restrict__ dst) {
    int e = blockIdx.x * blockDim.x + threadIdx.x;
    if (e < EE) {
        int p = atomicAdd(&g_rowcur[dst[e]], 1);
        g_srcs[p] = src[e];
    }
}

__global__ void sort_kernel() {
    int d = blockIdx.x * blockDim.x + threadIdx.x;
    if (d >= NN) return;
    int s = g_rowptr[d], e = g_rowptr[d + 1];
    for (int i = s + 1; i < e; i++) {
        int v = g_srcs[i];
        int j = i - 1;
        while (j >= s && g_srcs[j] > v) { g_srcs[j + 1] = g_srcs[j]; j--; }
        g_srcs[j + 1] = v;
    }
}

// ---------------- B repacks ----------------
__global__ void repack_sage_b(const float* __restrict__ wl, const float* __restrict__ wr) {
    int idx = blockIdx.x * blockDim.x + threadIdx.x;  // 128*128
    int r = idx >> 7, c = idx & 127;
    g_Bsage[idx] = (r < 64) ? wl[r * 128 + c] : wr[(r - 64) * 128 + c];
}

__global__ void repack_gat_b(const float* __restrict__ W) {
    int idx = blockIdx.x * blockDim.x + threadIdx.x;  // 512*256
    if (idx >= 512 * 256) return;
    int r = idx >> 8, c = idx & 255;
    int h = r >> 7, k = r & 127;
    g_Bgat[idx] = W[k * 1024 + h * 256 + c];
}

// ---------------- aggregation (CSR, one block per dst) ----------------
template <int C, int TPB, bool SAGE>
__global__ void agg_kernel(const float* __restrict__ feat, float* __restrict__ out,
                           int fs, int foff, int os) {
    constexpr int NPC = (C + TPB - 1) / TPB;
    int d = blockIdx.x;
    int t = threadIdx.x;
    int start = g_rowptr[d], end = g_rowptr[d + 1];
    float acc[NPC];
    if (!SAGE) {
        float dd = g_dis[d];
#pragma unroll
        for (int i = 0; i < NPC; i++) {
            int c = t + i * TPB;
            acc[i] = (c < C) ? dd * dd * feat[(size_t)d * fs + foff + c] : 0.f;
        }
        for (int p = start; p < end; p++) {
            int s = g_srcs[p];
            float w = g_dis[s] * dd;
#pragma unroll
            for (int i = 0; i < NPC; i++) {
                int c = t + i * TPB;
                if (c < C) acc[i] += w * feat[(size_t)s * fs + foff + c];
            }
        }
    } else {
#pragma unroll
        for (int i = 0; i < NPC; i++) acc[i] = 0.f;
        for (int p = start; p < end; p++) {
            int s = g_srcs[p];
#pragma unroll
            for (int i = 0; i < NPC; i++) {
                int c = t + i * TPB;
                if (c < C) acc[i] += feat[(size_t)s * fs + foff + c];
            }
        }
        float inv = 1.f / fmaxf((float)(end - start), 1.f);
#pragma unroll
        for (int i = 0; i < NPC; i++) acc[i] *= inv;
    }
#pragma unroll
    for (int i = 0; i < NPC; i++) {
        int c = t + i * TPB;
        if (c < C) out[(size_t)d * os + c] = acc[i];
    }
}

// ---------------- GEMMs ----------------
__global__ void gemm_k5(const float* __restrict__ A, const float* __restrict__ B,
                        float* __restrict__ C) {
    int idx = blockIdx.x * blockDim.x + threadIdx.x;  // NN*64
    int n = idx >> 6, j = idx & 63;
    const float* a = A + n * 5;
    float acc = a[0] * B[j] + a[1] * B[64 + j] + a[2] * B[128 + j] +
                a[3] * B[192 + j] + a[4] * B[256 + j];
    C[idx] = acc;
}

__device__ __forceinline__ unsigned f2tf(float f) {
    unsigned u;
    asm("cvt.rna.tf32.f32 %0, %1;" : "=r"(u) : "f"(f));
    return u;
}

// C[M,N] = A[M,K] @ B[K,N], tf32 tensor cores. M%128==0, N%128==0, K%32==0.
__global__ __launch_bounds__(256) void gemm_tf32(
    const float* __restrict__ A, int lda,
    const float* __restrict__ B, int ldb,
    float* __restrict__ C, int ldc,
    int M, int N, int K) {
    __shared__ unsigned As[32][132];  // k-major (transposed)
    __shared__ unsigned Bs[32][132];
    int tid = threadIdx.x;
    int bm = blockIdx.y * 128;
    int bn = blockIdx.x * 128;
    int w = tid >> 5, lane = tid & 31;
    int wm = (w & 3) * 32;   // warp row offset in tile
    int wn = (w >> 2) * 64;  // warp col offset in tile
    int g = lane >> 2;       // groupID (0..7)
    int tg = lane & 3;       // thread-in-group (0..3)

    float acc[2][8][4];
#pragma unroll
    for (int mi = 0; mi < 2; mi++)
#pragma unroll
        for (int ni = 0; ni < 8; ni++)
#pragma unroll
            for (int q = 0; q < 4; q++) acc[mi][ni][q] = 0.f;

    int arow = tid & 127, akq = tid >> 7;     // akq 0..1
    int bkr = tid >> 3;                       // 0..31
    int bcol = (tid & 7) * 16;

    for (int kt = 0; kt < K; kt += 32) {
#pragma unroll
        for (int i = 0; i < 4; i++) {
            int kk = akq * 16 + i * 4;
            float4 v = *reinterpret_cast<const float4*>(
                A + (size_t)(bm + arow) * lda + kt + kk);
            As[kk + 0][arow] = f2tf(v.x);
            As[kk + 1][arow] = f2tf(v.y);
            As[kk + 2][arow] = f2tf(v.z);
            As[kk + 3][arow] = f2tf(v.w);
        }
#pragma unroll
        for (int i = 0; i < 4; i++) {
            float4 v = *reinterpret_cast<const float4*>(
                B + (size_t)(kt + bkr) * ldb + bn + bcol + i * 4);
            Bs[bkr][bcol + i * 4 + 0] = f2tf(v.x);
            Bs[bkr][bcol + i * 4 + 1] = f2tf(v.y);
            Bs[bkr][bcol + i * 4 + 2] = f2tf(v.z);
            Bs[bkr][bcol + i * 4 + 3] = f2tf(v.w);
        }
        __syncthreads();
#pragma unroll
        for (int ks = 0; ks < 4; ks++) {
            int k0 = ks * 8;
            unsigned a[2][4], b[8][2];
#pragma unroll
            for (int mi = 0; mi < 2; mi++) {
                int r = wm + mi * 16;
                a[mi][0] = As[k0 + tg][r + g];
                a[mi][1] = As[k0 + tg][r + g + 8];
                a[mi][2] = As[k0 + tg + 4][r + g];
                a[mi][3] = As[k0 + tg + 4][r + g + 8];
            }
#pragma unroll
            for (int ni = 0; ni < 8; ni++) {
                b[ni][0] = Bs[k0 + tg][wn + ni * 8 + g];
                b[ni][1] = Bs[k0 + tg + 4][wn + ni * 8 + g];
            }
#pragma unroll
            for (int mi = 0; mi < 2; mi++)
#pragma unroll
                for (int ni = 0; ni < 8; ni++)
                    asm volatile(
                        "mma.sync.aligned.m16n8k8.row.col.f32.tf32.tf32.f32 "
                        "{%0,%1,%2,%3}, {%4,%5,%6,%7}, {%8,%9}, {%0,%1,%2,%3};"
                        : "+f"(acc[mi][ni][0]), "+f"(acc[mi][ni][1]),
                          "+f"(acc[mi][ni][2]), "+f"(acc[mi][ni][3])
                        : "r"(a[mi][0]), "r"(a[mi][1]), "r"(a[mi][2]), "r"(a[mi][3]),
                          "r"(b[ni][0]), "r"(b[ni][1]));
        }
        __syncthreads();
    }
#pragma unroll
    for (int mi = 0; mi < 2; mi++) {
#pragma unroll
        for (int ni = 0; ni < 8; ni++) {
            int row = bm + wm + mi * 16 + g;
            int col = bn + wn + ni * 8 + 2 * tg;
            float2 v0 = make_float2(acc[mi][ni][0], acc[mi][ni][1]);
            float2 v1 = make_float2(acc[mi][ni][2], acc[mi][ni][3]);
            *reinterpret_cast<float2*>(C + (size_t)row * ldc + col) = v0;
            *reinterpret_cast<float2*>(C + (size_t)(row + 8) * ldc + col) = v1;
        }
    }
}

// ---------------- batchnorm (deterministic two-level reduction) ----------------
__global__ void bn_stats(const float* __restrict__ x, int C) {
    int tid = threadIdx.x;
    int cw = C < 256 ? C : 256;
    int groups = 256 / cw;
    int lc = tid % cw, grp = tid / cw;
    int rpb = NN / 128;
    int r0 = blockIdx.x * rpb;
    float s0 = 0, q0 = 0, s1 = 0, q1 = 0;
    for (int r = r0 + grp; r < r0 + rpb; r += groups) {
        float v = x[(size_t)r * C + lc];
        s0 += v; q0 += v * v;
        if (C == 512) {
            float w2 = x[(size_t)r * C + lc + 256];
            s1 += w2; q1 += w2 * w2;
        }
    }
    __shared__ float ss[256], sq[256];
    ss[tid] = s0; sq[tid] = q0;
    __syncthreads();
    if (grp == 0) {
        for (int g2 = 1; g2 < groups; g2++) { s0 += ss[g2 * cw + lc]; q0 += sq[g2 * cw + lc]; }
        g_bnps[blockIdx.x * 512 + lc] = s0;
        g_bnpq[blockIdx.x * 512 + lc] = q0;
        if (C == 512) {
            g_bnps[blockIdx.x * 512 + lc + 256] = s1;
            g_bnpq[blockIdx.x * 512 + lc + 256] = q1;
        }
    }
}

__global__ void bn_finalize(int C) {
    int c = blockIdx.x * blockDim.x + threadIdx.x;
    if (c >= C) return;
    float s = 0, q = 0;
    for (int b = 0; b < 128; b++) { s += g_bnps[b * 512 + c]; q += g_bnpq[b * 512 + c]; }
    float mu = s * (1.f / NN);
    float var = q * (1.f / NN) - mu * mu;
    g_mu[c] = mu;
    g_rstd[c] = rsqrtf(var + 1e-5f);
}

// y[row*ostride + ooff + c] = relu(bn(x[row*C + c]))
__global__ void bn_apply(const float* __restrict__ x, float* __restrict__ y,
                         const float* __restrict__ g, const float* __restrict__ b,
                         int Cm1, int shift, int ostride, int ooff, int total) {
    int idx = blockIdx.x * blockDim.x + threadIdx.x;
    if (idx >= total) return;
    int c = idx & Cm1;
    int row = idx >> shift;
    float v = fmaxf(0.f, (x[idx] - g_mu[c]) * g_rstd[c] * g[c] + b[c]);
    y[(size_t)row * ostride + ooff + c] = v;
}

// ---------------- GAT ----------------
__global__ void vsd_kernel(const float* __restrict__ W, const float* __restrict__ asrc,
                           const float* __restrict__ adst) {
    int idx = blockIdx.x * blockDim.x + threadIdx.x;
    if (idx >= 512) return;
    int h = idx >> 7, k = idx & 127;
    float a = 0, b = 0;
    const float* wr = W + (size_t)k * 1024 + h * 256;
    const float* as = asrc + h * 256;
    const float* ad = adst + h * 256;
    for (int j = 0; j < 256; j++) { float w = wr[j]; a += w * as[j]; b += w * ad[j]; }
    g_vsrc[idx] = a;
    g_vdst[idx] = b;
}

__global__ void esed_kernel(const float* __restrict__ h2) {
    int idx = blockIdx.x * blockDim.x + threadIdx.x;
    if (idx >= NN * 4) return;
    int n = idx >> 2, h = idx & 3;
    const float* r = h2 + (size_t)n * 128;
    const float* vs = g_vsrc + h * 128;
    const float* vd = g_vdst + h * 128;
    float a = 0, b = 0;
#pragma unroll 8
    for (int k = 0; k < 128; k++) { float x = r[k]; a += x * vs[k]; b += x * vd[k]; }
    g_es[idx] = a;
    g_ed[idx] = b;
}

__device__ __forceinline__ float lrelu(float x) { return x > 0.f ? x : 0.2f * x; }

__global__ void gat_agg_kernel(const float* __restrict__ h2) {
    int d = blockIdx.x;
    int t = threadIdx.x;  // 128
    int start = g_rowptr[d], end = g_rowptr[d + 1];
    float edv[4], esd[4], m[4];
#pragma unroll
    for (int h = 0; h < 4; h++) {
        edv[h] = g_ed[d * 4 + h];
        esd[h] = g_es[d * 4 + h];
        m[h] = lrelu(esd[h] + edv[h]);
    }
    for (int p = start; p < end; p++) {
        int s = g_srcs[p];
#pragma unroll
        for (int h = 0; h < 4; h++) m[h] = fmaxf(m[h], lrelu(g_es[s * 4 + h] + edv[h]));
    }
    float z[4], acc[4];
    float hv = h2[(size_t)d * 128 + t];
#pragma unroll
    for (int h = 0; h < 4; h++) {
        float ex = expf(lrelu(esd[h] + edv[h]) - m[h]);
        z[h] = ex;
        acc[h] = ex * hv;
    }
    for (int p = start; p < end; p++) {
        int s = g_srcs[p];
        float sv = h2[(size_t)s * 128 + t];
#pragma unroll
        for (int h = 0; h < 4; h++) {
            float ex = expf(lrelu(g_es[s * 4 + h] + edv[h]) - m[h]);
            z[h] += ex;
            acc[h] += ex * sv;
        }
    }
#pragma unroll
    for (int h = 0; h < 4; h++)
        g_gatagg[(size_t)d * 512 + h * 128 + t] = acc[h] / z[h];
}

// ---------------- pooling + FC ----------------
__global__ void count_batch_kernel(const int* __restrict__ batch) {
    int i = blockIdx.x * blockDim.x + threadIdx.x;
    if (i < NN) atomicAdd(&g_gcnt[batch[i]], 1);
}

__global__ void pool_kernel() {
    int g = blockIdx.x, c = threadIdx.x;  // 32 blocks x 512 threads
    int start = 0;
    for (int i = 0; i < g; i++) start += g_gcnt[i];
    int cnt = g_gcnt[g];
    float s = 0.f, mx = -3.402823e38f;
    for (int r = start; r < start + cnt; r++) {
        float v = g_h4[(size_t)r * 512 + c];
        s += v;
        mx = fmaxf(mx, v);
    }
    g_pooled[g * 1024 + c] = s / fmaxf((float)cnt, 1.f);
    g_pooled[g * 1024 + 512 + c] = (cnt > 0) ? mx : 0.f;
}

__global__ void fc_kernel(const float* __restrict__ w, const float* __restrict__ bias,
                          float* __restrict__ out) {
    __shared__ float pt[32 * 128];
    int jb = blockIdx.x * 32;
    int j = jb + (threadIdx.x & 31);
    int gq = threadIdx.x >> 5;
    float acc[4] = {0, 0, 0, 0};
    for (int kt = 0; kt < 1024; kt += 128) {
        __syncthreads();
        for (int i = threadIdx.x; i < 4096; i += 256) {
            int g = i >> 7, kk = i & 127;
            pt[g * 128 + kk] = g_pooled[g * 1024 + kt + kk];
        }
        __syncthreads();
        for (int kk = 0; kk < 128; kk++) {
            float wv = w[(size_t)(kt + kk) * 1024 + j];
#pragma unroll
            for (int i = 0; i < 4; i++) acc[i] += pt[(gq * 4 + i) * 128 + kk] * wv;
        }
    }
#pragma unroll
    for (int i = 0; i < 4; i++) out[(gq * 4 + i) * 1024 + j] = acc[i] + bias[j];
}

// ---------------- driver ----------------
extern "C" void kernel_launch(void* const* d_in, const int* in_sizes, int n_in,
                              void* d_out, int out_size) {
    const float* x        = (const float*)d_in[0];
    const int*   eidx     = (const int*)d_in[1];
    const int*   batch    = (const int*)d_in[2];
    const float* gcn1_w   = (const float*)d_in[3];
    const float* sage_wl  = (const float*)d_in[5];
    const float* sage_wr  = (const float*)d_in[6];
    const float* gat_w    = (const float*)d_in[8];
    const float* gat_asrc = (const float*)d_in[9];
    const float* gat_adst = (const float*)d_in[10];
    const float* gcn4_w   = (const float*)d_in[12];
    const float* bn1_g = (const float*)d_in[14], *bn1_b = (const float*)d_in[15];
    const float* bn2_g = (const float*)d_in[16], *bn2_b = (const float*)d_in[17];
    const float* bn3_g = (const float*)d_in[18], *bn3_b = (const float*)d_in[19];
    const float* bn4_g = (const float*)d_in[20], *bn4_b = (const float*)d_in[21];
    const float* fc_w = (const float*)d_in[22], *fc_b = (const float*)d_in[23];
    const int* src = eidx;
    const int* dst = eidx + EE;
    float* out = (float*)d_out;

    float *agg0, *h1raw, *cat2, *h2raw, *h2, *gatagg, *h3raw, *h3, *gcn4agg, *h4raw, *h4;
    float *Bsage, *Bgat;
    cudaGetSymbolAddress((void**)&agg0, g_agg0);
    cudaGetSymbolAddress((void**)&h1raw, g_h1raw);
    cudaGetSymbolAddress((void**)&cat2, g_cat2);
    cudaGetSymbolAddress((void**)&h2raw, g_h2raw);
    cudaGetSymbolAddress((void**)&h2, g_h2);
    cudaGetSymbolAddress((void**)&gatagg, g_gatagg);
    cudaGetSymbolAddress((void**)&h3raw, g_h3raw);
    cudaGetSymbolAddress((void**)&h3, g_h3);
    cudaGetSymbolAddress((void**)&gcn4agg, g_gcn4agg);
    cudaGetSymbolAddress((void**)&h4raw, g_h4raw);
    cudaGetSymbolAddress((void**)&h4, g_h4);
    cudaGetSymbolAddress((void**)&Bsage, g_Bsage);
    cudaGetSymbolAddress((void**)&Bgat, g_Bgat);

    // graph preprocessing + weight repacks
    init_kernel<<<64, 256>>>();
    count_deg_kernel<<<EE / 256, 256>>>(dst);
    scan_kernel<<<1, 1024>>>();
    dis_kernel<<<64, 256>>>();
    scatter_kernel<<<EE / 256, 256>>>(src, dst);
    sort_kernel<<<64, 256>>>();
    repack_sage_b<<<64, 256>>>(sage_wl, sage_wr);
    repack_gat_b<<<512, 256>>>(gat_w);

    // layer 1: GCN(5->64)
    agg_kernel<5, 32, false><<<NN, 32>>>(x, agg0, 5, 0, 5);
    gemm_k5<<<NN * 64 / 256, 256>>>(agg0, gcn1_w, h1raw);
    bn_stats<<<128, 256>>>(h1raw, 64);
    bn_finalize<<<1, 64>>>(64);
    // h1 goes into cat2 columns [64:128)
    bn_apply<<<NN * 64 / 256, 256>>>(h1raw, cat2, bn1_g, bn1_b, 63, 6, 128, 64, NN * 64);

    // layer 2: SAGE(64->128); sage agg into cat2 columns [0:64), one K=128 GEMM
    agg_kernel<64, 64, true><<<NN, 64>>>(cat2, cat2, 128, 64, 128);
    gemm_tf32<<<dim3(1, 128), 256>>>(cat2, 128, Bsage, 128, h2raw, 128, NN, 128, 128);
    bn_stats<<<128, 256>>>(h2raw, 128);
    bn_finalize<<<1, 128>>>(128);
    bn_apply<<<NN * 128 / 256, 256>>>(h2raw, h2, bn2_g, bn2_b, 127, 7, 128, 0, NN * 128);

    // layer 3: GAT(128->256, 4 heads): aggregate then ONE K=512 GEMM
    vsd_kernel<<<2, 256>>>(gat_w, gat_asrc, gat_adst);
    esed_kernel<<<NN * 4 / 256, 256>>>(h2);
    gat_agg_kernel<<<NN, 128>>>(h2);
    gemm_tf32<<<dim3(2, 128), 256>>>(gatagg, 512, Bgat, 256, h3raw, 256, NN, 256, 512);
    bn_stats<<<128, 256>>>(h3raw, 256);
    bn_finalize<<<1, 256>>>(256);
    bn_apply<<<NN * 256 / 256, 256>>>(h3raw, h3, bn3_g, bn3_b, 255, 8, 256, 0, NN * 256);

    // layer 4: GCN(256->512)
    agg_kernel<256, 256, false><<<NN, 256>>>(h3, gcn4agg, 256, 0, 256);
    gemm_tf32<<<dim3(4, 128), 256>>>(gcn4agg, 256, gcn4_w, 512, h4raw, 512, NN, 512, 256);
    bn_stats<<<128, 256>>>(h4raw, 512);
    bn_finalize<<<2, 256>>>(512);
    bn_apply<<<NN * 512 / 256, 256>>>(h4raw, h4, bn4_g, bn4_b, 511, 9, 512, 0, NN * 512);

    // pooling + FC
    count_batch_kernel<<<64, 256>>>(batch);
    pool_kernel<<<GG, 512>>>();
    fc_kernel<<<32, 256>>>(fc_w, fc_b, out);
}

// round 5
// speedup vs baseline: 1.4911x; 1.3115x over previous
#include <cuda_runtime.h>
#include <math.h>

#define NN 16384
#define EE 131072
#define GG 32

// ---------------- scratch (static __device__, no allocations) ----------------
__device__ int   g_indeg[NN];
__device__ int   g_rowptr[NN + 1];
__device__ int   g_rowcur[NN];
__device__ int   g_srcs[EE];
__device__ int   g_dstc[EE];
__device__ float g_dis[NN];

__device__ __align__(16) float g_agg0[NN * 5];
__device__ __align__(16) float g_h1raw[NN * 64];
__device__ __align__(16) float g_cat2[NN * 128];     // [:,0:64)=sage agg, [:,64:128)=h1
__device__ __align__(16) float g_h2raw[NN * 128];
__device__ __align__(16) float g_h2[NN * 128];
__device__ float g_vsrc[512];
__device__ float g_vdst[512];
__device__ __align__(16) float g_es[NN * 4];
__device__ __align__(16) float g_ed[NN * 4];
__device__ __align__(16) float g_mh[NN * 4];
__device__ __align__(16) float g_zi[NN * 4];
__device__ __align__(16) float g_aself[NN * 4];
__device__ __align__(16) float g_alpha[EE * 4];
__device__ __align__(16) float g_gatagg[NN * 512];
__device__ __align__(16) float g_h3raw[NN * 256];
__device__ __align__(16) float g_gcn4agg[NN * 256];
__device__ __align__(16) float g_h4raw[NN * 512];

__device__ __align__(16) float g_Bsage[128 * 128];   // [wl;wr] stacked
__device__ __align__(16) float g_Bgat[512 * 256];    // head-stacked gat_w

__device__ float g_bnps[128 * 512];
__device__ float g_bnpq[128 * 512];
__device__ float g_mu[512];
__device__ float g_rstd[512];
__device__ int   g_bnctr = 0;

__device__ int   g_gcnt[GG];
__device__ float g_pooled[GG * 1024];

// ---------------- setup: init + weight repacks (all independent) ----------------
__global__ void setup_kernel(const float* __restrict__ wl, const float* __restrict__ wr,
                             const float* __restrict__ W) {
    int idx = blockIdx.x * blockDim.x + threadIdx.x;   // 512*256 threads
    if (idx < NN) g_indeg[idx] = 0;
    if (idx < GG) g_gcnt[idx] = 0;
    if (idx < 128 * 128) {
        int r = idx >> 7, c = idx & 127;
        g_Bsage[idx] = (r < 64) ? wl[r * 128 + c] : wr[(r - 64) * 128 + c];
    }
    {
        int r = idx >> 8, c = idx & 255;
        int h = r >> 7, k = r & 127;
        g_Bgat[idx] = W[k * 1024 + h * 256 + c];
    }
}

__global__ void count_kernel(const int* __restrict__ dst, const int* __restrict__ batch) {
    int e = blockIdx.x * blockDim.x + threadIdx.x;
    if (e < EE) atomicAdd(&g_indeg[dst[e]], 1);
    if (e < NN) atomicAdd(&g_gcnt[batch[e]], 1);
}

__global__ void scan_kernel() {
    __shared__ int part[1024];
    int t = threadIdx.x;
    int base = t * 16;
    int loc[16];
    int s = 0;
#pragma unroll
    for (int i = 0; i < 16; i++) { loc[i] = s; s += g_indeg[base + i]; }
    part[t] = s;
    __syncthreads();
    for (int off = 1; off < 1024; off <<= 1) {
        int v = (t >= off) ? part[t - off] : 0;
        __syncthreads();
        part[t] += v;
        __syncthreads();
    }
    int pre = (t > 0) ? part[t - 1] : 0;
#pragma unroll
    for (int i = 0; i < 16; i++) {
        g_rowptr[base + i] = pre + loc[i];
        g_rowcur[base + i] = pre + loc[i];
    }
    if (t == 1023) g_rowptr[NN] = part[1023];
}

__global__ void scatter_dis_kernel(const int* __restrict__ src, const int* __restrict__ dst) {
    int e = blockIdx.x * blockDim.x + threadIdx.x;
    if (e < EE) {
        int d = dst[e];
        int p = atomicAdd(&g_rowcur[d], 1);
        g_srcs[p] = src[e];
        g_dstc[p] = d;
    }
    if (e < NN) g_dis[e] = rsqrtf((float)(g_indeg[e] + 1));
}

__global__ void sort_kernel() {
    int d = blockIdx.x * blockDim.x + threadIdx.x;
    if (d >= NN) return;
    int s = g_rowptr[d], e = g_rowptr[d + 1];
    for (int i = s + 1; i < e; i++) {
        int v = g_srcs[i];
        int j = i - 1;
        while (j >= s && g_srcs[j] > v) { g_srcs[j + 1] = g_srcs[j]; j--; }
        g_srcs[j + 1] = v;
    }
}

// ---------------- aggregations ----------------
// layer1: one thread per dst, 5 channels in registers
__global__ void agg5_kernel(const float* __restrict__ x) {
    int d = blockIdx.x * blockDim.x + threadIdx.x;
    if (d >= NN) return;
    float dd = g_dis[d];
    float acc[5];
#pragma unroll
    for (int c = 0; c < 5; c++) acc[c] = dd * dd * x[d * 5 + c];
    int st = g_rowptr[d], en = g_rowptr[d + 1];
#pragma unroll 2
    for (int p = st; p < en; p++) {
        int s = g_srcs[p];
        float w = g_dis[s] * dd;
#pragma unroll
        for (int c = 0; c < 5; c++) acc[c] += w * x[s * 5 + c];
    }
#pragma unroll
    for (int c = 0; c < 5; c++) g_agg0[d * 5 + c] = acc[c];
}

// SAGE mean agg: 4 dsts per 256-thread block, 64 channels each; srcs staged in smem
__global__ void agg_sage_kernel() {
    __shared__ int ssrc[4][32];
    __shared__ int smax;
    int tid = threadIdx.x;
    int ld = tid >> 6, c = tid & 63;
    int d = blockIdx.x * 4 + ld;
    int st = g_rowptr[d], en = g_rowptr[d + 1], deg = en - st;
    if (tid == 0) smax = 0;
    __syncthreads();
    if (c == 0) atomicMax(&smax, deg);
    __syncthreads();
    int chunks = (smax + 31) >> 5;
    float acc = 0.f;
    for (int ch = 0; ch < chunks; ch++) {
        int p0 = st + ch * 32;
        if (c < 32) ssrc[ld][c] = (p0 + c < en) ? g_srcs[p0 + c] : 0;
        __syncthreads();
        int cnt = min(32, en - p0);
#pragma unroll 4
        for (int j = 0; j < cnt; j++) {
            int s = ssrc[ld][j];
            acc += g_cat2[(size_t)s * 128 + 64 + c];
        }
        __syncthreads();
    }
    g_cat2[(size_t)d * 128 + c] = acc / fmaxf((float)deg, 1.f);
}

// GCN4 agg with BN3+relu fused (reads h3raw + layer-3 mu/rstd)
__global__ __launch_bounds__(256) void agg_gcn4_kernel(const float* __restrict__ bg,
                                                       const float* __restrict__ bb) {
    __shared__ int ssrc[32];
    __shared__ float sdis[32];
    int c = threadIdx.x;  // 256
    int d = blockIdx.x;
    float a = g_rstd[c] * bg[c];
    float b2 = bb[c] - g_mu[c] * a;
    int st = g_rowptr[d], en = g_rowptr[d + 1];
    float dd = g_dis[d];
    float sv = g_h3raw[(size_t)d * 256 + c];
    float acc = dd * dd * fmaxf(0.f, sv * a + b2);
    for (int p0 = st; p0 < en; p0 += 32) {
        if (c < 32) {
            int pp = p0 + c;
            int s = (pp < en) ? g_srcs[pp] : 0;
            ssrc[c] = s;
            sdis[c] = (pp < en) ? g_dis[s] : 0.f;
        }
        __syncthreads();
        int cnt = min(32, en - p0);
#pragma unroll 4
        for (int j = 0; j < cnt; j++) {
            int s = ssrc[j];
            float w = sdis[j] * dd;
            float v = g_h3raw[(size_t)s * 256 + c];
            acc += w * fmaxf(0.f, v * a + b2);
        }
        __syncthreads();
    }
    g_gcn4agg[(size_t)d * 256 + c] = acc;
}

// ---------------- GEMMs ----------------
__global__ void gemm_k5(const float* __restrict__ A, const float* __restrict__ B,
                        float* __restrict__ C) {
    int idx = blockIdx.x * blockDim.x + threadIdx.x;
    int n = idx >> 6, j = idx & 63;
    const float* a = A + n * 5;
    C[idx] = a[0] * B[j] + a[1] * B[64 + j] + a[2] * B[128 + j] +
             a[3] * B[192 + j] + a[4] * B[256 + j];
}

__device__ __forceinline__ unsigned f2tf(float f) {
    unsigned u;
    asm("cvt.rna.tf32.f32 %0, %1;" : "=r"(u) : "f"(f));
    return u;
}

#define CP16(saddr, gptr) \
    asm volatile("cp.async.cg.shared.global [%0], [%1], 16;" :: "r"(saddr), "l"(gptr))
#define CP_COMMIT() asm volatile("cp.async.commit_group;" ::: "memory")
#define CP_WAIT1() asm volatile("cp.async.wait_group 1;" ::: "memory")

// C[M,N] = A[M,K] @ B[K,N]; tf32 MMA, cp.async double-buffered. M%128==0, N%128==0, K%16==0.
__global__ __launch_bounds__(256) void gemm_tf32(
    const float* __restrict__ A, int lda,
    const float* __restrict__ B, int ldb,
    float* __restrict__ C, int ldc, int K) {
    __shared__ float As[2][128][20];   // row-major [m][k], pad 20
    __shared__ float Bs[2][16][136];   // [k][n], pad 136
    int tid = threadIdx.x;
    int bm = blockIdx.y * 128, bn = blockIdx.x * 128;
    int w = tid >> 5, lane = tid & 31;
    int wm = (w & 3) * 32, wn = (w >> 2) * 64;
    int g = lane >> 2, tg = lane & 3;

    float acc[2][8][4];
#pragma unroll
    for (int mi = 0; mi < 2; mi++)
#pragma unroll
        for (int ni = 0; ni < 8; ni++)
#pragma unroll
            for (int q = 0; q < 4; q++) acc[mi][ni][q] = 0.f;

    int arow = tid >> 2, ac4 = (tid & 3) * 4;
    int bkr = tid >> 5, bc4 = lane * 4;
    const float* apA = A + (size_t)(bm + arow) * lda + ac4;
    const float* apB = A + (size_t)(bm + arow + 64) * lda + ac4;
    const float* bpA = B + (size_t)bkr * ldb + bn + bc4;
    const float* bpB = B + (size_t)(bkr + 8) * ldb + bn + bc4;
    unsigned sA0 = (unsigned)__cvta_generic_to_shared(&As[0][arow][ac4]);
    unsigned sA1 = (unsigned)__cvta_generic_to_shared(&As[0][arow + 64][ac4]);
    unsigned sB0 = (unsigned)__cvta_generic_to_shared(&Bs[0][bkr][bc4]);
    unsigned sB1 = (unsigned)__cvta_generic_to_shared(&Bs[0][bkr + 8][bc4]);
    const unsigned stA = 128 * 20 * 4, stB = 16 * 136 * 4;
    int T = K >> 4;

#define PREFETCH(t, st_) do { \
    CP16(sA0 + (st_) * stA, apA + (t) * 16); \
    CP16(sA1 + (st_) * stA, apB + (t) * 16); \
    CP16(sB0 + (st_) * stB, bpA + (size_t)(t) * 16 * ldb); \
    CP16(sB1 + (st_) * stB, bpB + (size_t)(t) * 16 * ldb); } while (0)

    PREFETCH(0, 0);
    CP_COMMIT();
    if (T > 1) PREFETCH(1, 1);
    CP_COMMIT();

    for (int i = 0; i < T; i++) {
        CP_WAIT1();
        __syncthreads();
        int s = i & 1;
#pragma unroll
        for (int ks = 0; ks < 2; ks++) {
            int k0 = ks * 8;
            unsigned a[2][4], b[8][2];
#pragma unroll
            for (int mi = 0; mi < 2; mi++) {
                int r = wm + mi * 16;
                a[mi][0] = f2tf(As[s][r + g][k0 + tg]);
                a[mi][1] = f2tf(As[s][r + g + 8][k0 + tg]);
                a[mi][2] = f2tf(As[s][r + g][k0 + tg + 4]);
                a[mi][3] = f2tf(As[s][r + g + 8][k0 + tg + 4]);
            }
#pragma unroll
            for (int ni = 0; ni < 8; ni++) {
                b[ni][0] = f2tf(Bs[s][k0 + tg][wn + ni * 8 + g]);
                b[ni][1] = f2tf(Bs[s][k0 + tg + 4][wn + ni * 8 + g]);
            }
#pragma unroll
            for (int mi = 0; mi < 2; mi++)
#pragma unroll
                for (int ni = 0; ni < 8; ni++)
                    asm volatile(
                        "mma.sync.aligned.m16n8k8.row.col.f32.tf32.tf32.f32 "
                        "{%0,%1,%2,%3}, {%4,%5,%6,%7}, {%8,%9}, {%0,%1,%2,%3};"
                        : "+f"(acc[mi][ni][0]), "+f"(acc[mi][ni][1]),
                          "+f"(acc[mi][ni][2]), "+f"(acc[mi][ni][3])
                        : "r"(a[mi][0]), "r"(a[mi][1]), "r"(a[mi][2]), "r"(a[mi][3]),
                          "r"(b[ni][0]), "r"(b[ni][1]));
        }
        __syncthreads();
        if (i + 2 < T) PREFETCH(i + 2, s);
        CP_COMMIT();
    }
#pragma unroll
    for (int mi = 0; mi < 2; mi++) {
#pragma unroll
        for (int ni = 0; ni < 8; ni++) {
            int row = bm + wm + mi * 16 + g;
            int col = bn + wn + ni * 8 + 2 * tg;
            float2 v0 = make_float2(acc[mi][ni][0], acc[mi][ni][1]);
            float2 v1 = make_float2(acc[mi][ni][2], acc[mi][ni][3]);
            *reinterpret_cast<float2*>(C + (size_t)row * ldc + col) = v0;
            *reinterpret_cast<float2*>(C + (size_t)(row + 8) * ldc + col) = v1;
        }
    }
#undef PREFETCH
}

// ---------------- batchnorm: stats + in-kernel finalize (last block) ----------------
__global__ void bn_stats_fin(const float* __restrict__ x, int C) {
    int tid = threadIdx.x;
    int cw = C < 256 ? C : 256;
    int groups = 256 / cw;
    int lc = tid % cw, grp = tid / cw;
    int rpb = NN / 128;
    int r0 = blockIdx.x * rpb;
    float s0 = 0, q0 = 0, s1 = 0, q1 = 0;
    for (int r = r0 + grp; r < r0 + rpb; r += groups) {
        float v = x[(size_t)r * C + lc];
        s0 += v; q0 += v * v;
        if (C == 512) {
            float w2 = x[(size_t)r * C + lc + 256];
            s1 += w2; q1 += w2 * w2;
        }
    }
    __shared__ float ss[256], sq[256];
    ss[tid] = s0; sq[tid] = q0;
    __syncthreads();
    if (grp == 0) {
        for (int g2 = 1; g2 < groups; g2++) { s0 += ss[g2 * cw + lc]; q0 += sq[g2 * cw + lc]; }
        g_bnps[blockIdx.x * 512 + lc] = s0;
        g_bnpq[blockIdx.x * 512 + lc] = q0;
        if (C == 512) {
            g_bnps[blockIdx.x * 512 + lc + 256] = s1;
            g_bnpq[blockIdx.x * 512 + lc + 256] = q1;
        }
    }
    __threadfence();
    __syncthreads();
    __shared__ int slast;
    if (tid == 0) slast = (atomicAdd(&g_bnctr, 1) == 127) ? 1 : 0;
    __syncthreads();
    if (slast) {
        __threadfence();
        for (int c = tid; c < C; c += 256) {
            float s = 0, q = 0;
            for (int b = 0; b < 128; b++) { s += g_bnps[b * 512 + c]; q += g_bnpq[b * 512 + c]; }
            float mu = s * (1.f / NN);
            float var = q * (1.f / NN) - mu * mu;
            g_mu[c] = mu;
            g_rstd[c] = rsqrtf(var + 1e-5f);
        }
        if (tid == 0) g_bnctr = 0;
    }
}

// y[row*ostride + ooff + c] = relu(bn(x[row*C + c]))
__global__ void bn_apply(const float* __restrict__ x, float* __restrict__ y,
                         const float* __restrict__ g, const float* __restrict__ b,
                         int Cm1, int shift, int ostride, int ooff, int total) {
    int idx = blockIdx.x * blockDim.x + threadIdx.x;
    if (idx >= total) return;
    int c = idx & Cm1;
    int row = idx >> shift;
    float v = fmaxf(0.f, (x[idx] - g_mu[c]) * g_rstd[c] * g[c] + b[c]);
    y[(size_t)row * ostride + ooff + c] = v;
}

// ---------------- GAT ----------------
__global__ void vsd_kernel(const float* __restrict__ W, const float* __restrict__ asrc,
                           const float* __restrict__ adst) {
    int wid = (blockIdx.x * 256 + threadIdx.x) >> 5;  // 0..511
    int lane = threadIdx.x & 31;
    int h = wid >> 7, k = wid & 127;
    const float* wr = W + (size_t)k * 1024 + h * 256;
    const float* as = asrc + h * 256;
    const float* ad = adst + h * 256;
    float a = 0, b = 0;
    for (int j = lane; j < 256; j += 32) { float wv = wr[j]; a += wv * as[j]; b += wv * ad[j]; }
#pragma unroll
    for (int off = 16; off > 0; off >>= 1) {
        a += __shfl_down_sync(0xffffffff, a, off);
        b += __shfl_down_sync(0xffffffff, b, off);
    }
    if (lane == 0) { g_vsrc[wid] = a; g_vdst[wid] = b; }
}

__global__ void esed_kernel(const float* __restrict__ h2) {
    int idx = blockIdx.x * blockDim.x + threadIdx.x;
    if (idx >= NN * 4) return;
    int n = idx >> 2, h = idx & 3;
    const float* r = h2 + (size_t)n * 128;
    const float* vs = g_vsrc + h * 128;
    const float* vd = g_vdst + h * 128;
    float a = 0, b = 0;
#pragma unroll 8
    for (int k = 0; k < 128; k++) { float x = r[k]; a += x * vs[k]; b += x * vd[k]; }
    g_es[idx] = a;
    g_ed[idx] = b;
}

__device__ __forceinline__ float lrelu(float x) { return x > 0.f ? x : 0.2f * x; }

// per (dst, head): softmax max + normalizer + self-alpha
__global__ void gat_mz_kernel() {
    int idx = blockIdx.x * blockDim.x + threadIdx.x;
    if (idx >= NN * 4) return;
    int d = idx >> 2, h = idx & 3;
    float edv = g_ed[idx];
    float selfe = lrelu(g_es[idx] + edv);
    float m = selfe;
    int st = g_rowptr[d], en = g_rowptr[d + 1];
#pragma unroll 2
    for (int p = st; p < en; p++) {
        int s = g_srcs[p];
        m = fmaxf(m, lrelu(g_es[s * 4 + h] + edv));
    }
    float z = expf(selfe - m);
#pragma unroll 2
    for (int p = st; p < en; p++) {
        int s = g_srcs[p];
        z += expf(lrelu(g_es[s * 4 + h] + edv) - m);
    }
    float zi = 1.f / z;
    g_mh[idx] = m;
    g_zi[idx] = zi;
    g_aself[idx] = expf(selfe - m) * zi;
}

// per (csr position, head): normalized attention weight
__global__ void gat_alpha_kernel() {
    int idx = blockIdx.x * blockDim.x + threadIdx.x;
    if (idx >= EE * 4) return;
    int p = idx >> 2, h = idx & 3;
    int d = g_dstc[p], s = g_srcs[p];
    float e = lrelu(g_es[s * 4 + h] + g_ed[d * 4 + h]);
    g_alpha[idx] = expf(e - g_mh[d * 4 + h]) * g_zi[d * 4 + h];
}

// weighted gather: one dst per 128-thread block, all 4 heads per thread
__global__ __launch_bounds__(128) void gat_gather_kernel(const float* __restrict__ h2) {
    __shared__ int ssrc[32];
    __shared__ float4 salpha[32];
    int tid = threadIdx.x;
    int d = blockIdx.x;
    int st = g_rowptr[d], en = g_rowptr[d + 1];
    float hv = h2[(size_t)d * 128 + tid];
    float4 as4 = *reinterpret_cast<const float4*>(g_aself + d * 4);
    float a0 = as4.x * hv, a1 = as4.y * hv, a2 = as4.z * hv, a3 = as4.w * hv;
    for (int p0 = st; p0 < en; p0 += 32) {
        if (tid < 32) {
            int pp = p0 + tid;
            ssrc[tid] = (pp < en) ? g_srcs[pp] : 0;
        } else if (tid < 64) {
            int pp = p0 + tid - 32;
            salpha[tid - 32] = (pp < en)
                ? *reinterpret_cast<const float4*>(g_alpha + (size_t)pp * 4)
                : make_float4(0.f, 0.f, 0.f, 0.f);
        }
        __syncthreads();
        int cnt = min(32, en - p0);
#pragma unroll 2
        for (int j = 0; j < cnt; j++) {
            int s = ssrc[j];
            float sv = h2[(size_t)s * 128 + tid];
            float4 w4 = salpha[j];
            a0 += w4.x * sv; a1 += w4.y * sv; a2 += w4.z * sv; a3 += w4.w * sv;
        }
        __syncthreads();
    }
    size_t o = (size_t)d * 512 + tid;
    g_gatagg[o] = a0;
    g_gatagg[o + 128] = a1;
    g_gatagg[o + 256] = a2;
    g_gatagg[o + 384] = a3;
}

// ---------------- pooling (BN4+relu fused) + FC ----------------
__global__ void pool_kernel(const float* __restrict__ g4, const float* __restrict__ b4) {
    int g = blockIdx.x, c = threadIdx.x;  // 32 blocks x 512 threads
    float a = g_rstd[c] * g4[c];
    float b2 = b4[c] - g_mu[c] * a;
    int start = 0;
    for (int i = 0; i < g; i++) start += g_gcnt[i];
    int cnt = g_gcnt[g];
    float s = 0.f, mx = -3.402823e38f;
    for (int r = start; r < start + cnt; r++) {
        float v = fmaxf(0.f, g_h4raw[(size_t)r * 512 + c] * a + b2);
        s += v;
        mx = fmaxf(mx, v);
    }
    g_pooled[g * 1024 + c] = s / fmaxf((float)cnt, 1.f);
    g_pooled[g * 1024 + 512 + c] = (cnt > 0) ? mx : 0.f;
}

__global__ void fc_kernel(const float* __restrict__ w, const float* __restrict__ bias,
                          float* __restrict__ out) {
    __shared__ float pt[32 * 128];
    int jb = blockIdx.x * 32;
    int j = jb + (threadIdx.x & 31);
    int gq = threadIdx.x >> 5;
    float acc[4] = {0, 0, 0, 0};
    for (int kt = 0; kt < 1024; kt += 128) {
        __syncthreads();
        for (int i = threadIdx.x; i < 4096; i += 256) {
            int g = i >> 7, kk = i & 127;
            pt[g * 128 + kk] = g_pooled[g * 1024 + kt + kk];
        }
        __syncthreads();
        for (int kk = 0; kk < 128; kk++) {
            float wv = w[(size_t)(kt + kk) * 1024 + j];
#pragma unroll
            for (int i = 0; i < 4; i++) acc[i] += pt[(gq * 4 + i) * 128 + kk] * wv;
        }
    }
#pragma unroll
    for (int i = 0; i < 4; i++) out[(gq * 4 + i) * 1024 + j] = acc[i] + bias[j];
}

// ---------------- driver ----------------
extern "C" void kernel_launch(void* const* d_in, const int* in_sizes, int n_in,
                              void* d_out, int out_size) {
    const float* x        = (const float*)d_in[0];
    const int*   eidx     = (const int*)d_in[1];
    const int*   batch    = (const int*)d_in[2];
    const float* gcn1_w   = (const float*)d_in[3];
    const float* sage_wl  = (const float*)d_in[5];
    const float* sage_wr  = (const float*)d_in[6];
    const float* gat_w    = (const float*)d_in[8];
    const float* gat_asrc = (const float*)d_in[9];
    const float* gat_adst = (const float*)d_in[10];
    const float* gcn4_w   = (const float*)d_in[12];
    const float* bn1_g = (const float*)d_in[14], *bn1_b = (const float*)d_in[15];
    const float* bn2_g = (const float*)d_in[16], *bn2_b = (const float*)d_in[17];
    const float* bn3_g = (const float*)d_in[18], *bn3_b = (const float*)d_in[19];
    const float* bn4_g = (const float*)d_in[20], *bn4_b = (const float*)d_in[21];
    const float* fc_w = (const float*)d_in[22], *fc_b = (const float*)d_in[23];
    const int* src = eidx;
    const int* dst = eidx + EE;
    float* out = (float*)d_out;

    float *agg0, *h1raw, *cat2, *h2raw, *h2, *gatagg, *h3raw, *gcn4agg, *h4raw;
    float *Bsage, *Bgat;
    cudaGetSymbolAddress((void**)&agg0, g_agg0);
    cudaGetSymbolAddress((void**)&h1raw, g_h1raw);
    cudaGetSymbolAddress((void**)&cat2, g_cat2);
    cudaGetSymbolAddress((void**)&h2raw, g_h2raw);
    cudaGetSymbolAddress((void**)&h2, g_h2);
    cudaGetSymbolAddress((void**)&gatagg, g_gatagg);
    cudaGetSymbolAddress((void**)&h3raw, g_h3raw);
    cudaGetSymbolAddress((void**)&gcn4agg, g_gcn4agg);
    cudaGetSymbolAddress((void**)&h4raw, g_h4raw);
    cudaGetSymbolAddress((void**)&Bsage, g_Bsage);
    cudaGetSymbolAddress((void**)&Bgat, g_Bgat);

    // preprocessing
    setup_kernel<<<512, 256>>>(sage_wl, sage_wr, gat_w);
    count_kernel<<<512, 256>>>(dst, batch);
    scan_kernel<<<1, 1024>>>();
    scatter_dis_kernel<<<512, 256>>>(src, dst);
    sort_kernel<<<64, 256>>>();

    // layer 1: GCN(5->64)
    agg5_kernel<<<64, 256>>>(x);
    gemm_k5<<<NN * 64 / 256, 256>>>(agg0, gcn1_w, h1raw);
    bn_stats_fin<<<128, 256>>>(h1raw, 64);
    bn_apply<<<NN * 64 / 256, 256>>>(h1raw, cat2, bn1_g, bn1_b, 63, 6, 128, 64, NN * 64);

    // layer 2: SAGE(64->128), one K=128 GEMM on [agg|h1]
    agg_sage_kernel<<<NN / 4, 256>>>();
    gemm_tf32<<<dim3(1, 128), 256>>>(cat2, 128, Bsage, 128, h2raw, 128, 128);
    bn_stats_fin<<<128, 256>>>(h2raw, 128);
    bn_apply<<<NN * 128 / 256, 256>>>(h2raw, h2, bn2_g, bn2_b, 127, 7, 128, 0, NN * 128);

    // layer 3: GAT(128->256, 4 heads): alpha precompute, gather, one K=512 GEMM
    vsd_kernel<<<64, 256>>>(gat_w, gat_asrc, gat_adst);
    esed_kernel<<<NN * 4 / 256, 256>>>(h2);
    gat_mz_kernel<<<NN * 4 / 256, 256>>>();
    gat_alpha_kernel<<<EE * 4 / 256, 256>>>();
    gat_gather_kernel<<<NN, 128>>>(h2);
    gemm_tf32<<<dim3(2, 128), 256>>>(gatagg, 512, Bgat, 256, h3raw, 256, 512);
    bn_stats_fin<<<128, 256>>>(h3raw, 256);

    // layer 4: GCN(256->512): BN3+relu fused into aggregation
    agg_gcn4_kernel<<<NN, 256>>>(bn3_g, bn3_b);
    gemm_tf32<<<dim3(4, 128), 256>>>(gcn4agg, 256, gcn4_w, 512, h4raw, 512, 256);
    bn_stats_fin<<<128, 256>>>(h4raw, 512);

    // pooling (BN4 fused) + FC
    pool_kernel<<<GG, 512>>>(bn4_g, bn4_b);
    fc_kernel<<<32, 256>>>(fc_w, fc_b, out);
}

// round 12
// speedup vs baseline: 1.9331x; 1.2964x over previous
#include <cuda_runtime.h>
#include <math.h>

#define NN 16384
#define EE 131072
#define GG 32

// ---------------- scratch (static __device__, no allocations) ----------------
__device__ int   g_indeg[NN];
__device__ int   g_rowptr[NN + 1];
__device__ int   g_rowcur[NN];
__device__ int   g_srcs[EE];
__device__ float g_dis[NN];

__device__ __align__(16) float g_agg0[NN * 5];
__device__ __align__(16) float g_h1raw[NN * 64];
__device__ __align__(16) float g_cat2[NN * 128];     // [:,0:64)=sage agg, [:,64:128)=h1
__device__ __align__(16) float g_h2raw[NN * 128];
__device__ __align__(16) float g_h2[NN * 128];
__device__ float g_vsrc[512];
__device__ float g_vdst[512];
__device__ __align__(16) float g_es[NN * 4];
__device__ __align__(16) float g_ed[NN * 4];
__device__ __align__(16) float g_mh[NN * 4];
__device__ __align__(16) float g_zi[NN * 4];
__device__ __align__(16) float g_aself[NN * 4];
__device__ __align__(16) float g_gatagg[NN * 512];
__device__ __align__(16) float g_h3raw[NN * 256];
__device__ __align__(16) float g_gcn4agg[NN * 256];
__device__ __align__(16) float g_h4raw[NN * 512];

__device__ __align__(16) float g_Bsage[128 * 128];   // [wl;wr] stacked
__device__ __align__(16) float g_Bgat[512 * 256];    // head-stacked gat_w

__device__ float g_bnps[128 * 512];
__device__ float g_bnpq[128 * 512];
__device__ float g_mu[512];
__device__ float g_rstd[512];
__device__ int   g_bnctr = 0;

__device__ int   g_gcnt[GG];
__device__ float g_pooled[GG * 1024];

// last-block BN finalize. ORDER MATTERS: fence -> syncthreads -> atomic
// (each writer fences its own partials; the barrier ensures all fences
// complete before thread 0 announces arrival).
__device__ __forceinline__ void bn_finalize_tail(int C, int expected, int tid) {
    __threadfence();
    __syncthreads();
    __shared__ int slast;
    if (tid == 0) slast = (atomicAdd(&g_bnctr, 1) == expected - 1) ? 1 : 0;
    __syncthreads();
    if (slast) {
        __threadfence();
        for (int c = tid; c < C; c += blockDim.x) {
            float s = 0.f, q = 0.f;
            for (int b = 0; b < 128; b++) { s += g_bnps[b * 512 + c]; q += g_bnpq[b * 512 + c]; }
            float mu = s * (1.f / NN);
            float var = q * (1.f / NN) - mu * mu;
            g_mu[c] = mu;
            g_rstd[c] = rsqrtf(var + 1e-5f);
        }
        __threadfence();
        if (tid == 0) g_bnctr = 0;
    }
}

// ---------------- setup / graph preprocessing ----------------
__global__ void setup_kernel(const float* __restrict__ wl, const float* __restrict__ wr,
                             const float* __restrict__ W) {
    int idx = blockIdx.x * blockDim.x + threadIdx.x;   // 512*256 threads
    if (idx < NN) g_indeg[idx] = 0;
    if (idx < GG) g_gcnt[idx] = 0;
    if (idx < 128 * 128) {
        int r = idx >> 7, c = idx & 127;
        g_Bsage[idx] = (r < 64) ? wl[r * 128 + c] : wr[(r - 64) * 128 + c];
    }
    {
        int r = idx >> 8, c = idx & 255;
        int h = r >> 7, k = r & 127;
        g_Bgat[idx] = W[k * 1024 + h * 256 + c];
    }
}

__global__ void count_kernel(const int* __restrict__ dst, const int* __restrict__ batch) {
    int e = blockIdx.x * blockDim.x + threadIdx.x;
    if (e < EE) atomicAdd(&g_indeg[dst[e]], 1);
    if (e < NN) atomicAdd(&g_gcnt[batch[e]], 1);
}

__global__ void scan_kernel() {
    __shared__ int part[1024];
    int t = threadIdx.x;
    int base = t * 16;
    int loc[16];
    int s = 0;
#pragma unroll
    for (int i = 0; i < 16; i++) { loc[i] = s; s += g_indeg[base + i]; }
    part[t] = s;
    __syncthreads();
    for (int off = 1; off < 1024; off <<= 1) {
        int v = (t >= off) ? part[t - off] : 0;
        __syncthreads();
        part[t] += v;
        __syncthreads();
    }
    int pre = (t > 0) ? part[t - 1] : 0;
#pragma unroll
    for (int i = 0; i < 16; i++) {
        g_rowptr[base + i] = pre + loc[i];
        g_rowcur[base + i] = pre + loc[i];
    }
    if (t == 1023) g_rowptr[NN] = part[1023];
}

__global__ void scatter_dis_kernel(const int* __restrict__ src, const int* __restrict__ dst) {
    int e = blockIdx.x * blockDim.x + threadIdx.x;
    if (e < EE) {
        int d = dst[e];
        int p = atomicAdd(&g_rowcur[d], 1);
        g_srcs[p] = src[e];
    }
    if (e < NN) g_dis[e] = rsqrtf((float)(g_indeg[e] + 1));
}

// warp-per-node odd-even sort in smem (canonical deterministic order)
__global__ void sort_kernel() {
    __shared__ int buf[8][64];
    int wrp = threadIdx.x >> 5, lane = threadIdx.x & 31;
    int d = blockIdx.x * 8 + wrp;
    int st = g_rowptr[d], en = g_rowptr[d + 1], n = en - st;
    if (n <= 1) return;
    if (n <= 64) {
        int* b = buf[wrp];
        for (int i = lane; i < 64; i += 32) b[i] = (i < n) ? g_srcs[st + i] : 0x7fffffff;
        __syncwarp();
        int npass = n + (n & 1);
        for (int pass = 0; pass < npass; pass++) {
            int i = (pass & 1) + 2 * lane;
            if (i + 1 < 64) {
                int a = b[i], c = b[i + 1];
                if (a > c) { b[i] = c; b[i + 1] = a; }
            }
            __syncwarp();
        }
        for (int i = lane; i < n; i += 32) g_srcs[st + i] = b[i];
    } else if (lane == 0) {
        for (int i = st + 1; i < en; i++) {
            int v = g_srcs[i], j = i - 1;
            while (j >= st && g_srcs[j] > v) { g_srcs[j + 1] = g_srcs[j]; j--; }
            g_srcs[j + 1] = v;
        }
    }
}

// ---------------- layer 1: GCN(5->64) ----------------
__global__ void agg5_kernel(const float* __restrict__ x) {
    int d = blockIdx.x * blockDim.x + threadIdx.x;
    if (d >= NN) return;
    float dd = g_dis[d];
    float acc[5];
#pragma unroll
    for (int c = 0; c < 5; c++) acc[c] = dd * dd * x[d * 5 + c];
    int st = g_rowptr[d], en = g_rowptr[d + 1];
#pragma unroll 2
    for (int p = st; p < en; p++) {
        int s = g_srcs[p];
        float w = g_dis[s] * dd;
#pragma unroll
        for (int c = 0; c < 5; c++) acc[c] += w * x[s * 5 + c];
    }
#pragma unroll
    for (int c = 0; c < 5; c++) g_agg0[d * 5 + c] = acc[c];
}

// small GEMM (K=5) with fused BN1 stats. grid=128, block=256 (4 row-groups x 64 cols)
__global__ void gemm_k5_bn(const float* __restrict__ A, const float* __restrict__ B) {
    __shared__ float sB[320];
    __shared__ float ssum[4][64], ssq[4][64];
    int tid = threadIdx.x;
    for (int i = tid; i < 320; i += 256) sB[i] = B[i];   // FIX: full 320-element load
    __syncthreads();
    int grp = tid >> 6, c = tid & 63;
    int r0 = blockIdx.x * 128;
    float s = 0.f, q = 0.f;
    for (int r = r0 + grp; r < r0 + 128; r += 4) {
        const float* a = A + r * 5;
        float v = a[0] * sB[c] + a[1] * sB[64 + c] + a[2] * sB[128 + c] +
                  a[3] * sB[192 + c] + a[4] * sB[256 + c];
        g_h1raw[r * 64 + c] = v;
        s += v; q += v * v;
    }
    ssum[grp][c] = s; ssq[grp][c] = q;
    __syncthreads();
    if (grp == 0) {
        for (int g2 = 1; g2 < 4; g2++) { s += ssum[g2][c]; q += ssq[g2][c]; }
        g_bnps[blockIdx.x * 512 + c] = s;
        g_bnpq[blockIdx.x * 512 + c] = q;
    }
    bn_finalize_tail(64, 128, tid);
}

// ---------------- layer 2: SAGE agg with BN1+relu fused; warp per dst ----------------
__global__ void agg_sage_bn1(const float* __restrict__ g1, const float* __restrict__ b1) {
    int lane = threadIdx.x & 31;
    int d = blockIdx.x * 8 + (threadIdx.x >> 5);
    float a0 = g_rstd[lane] * g1[lane];
    float bb0 = b1[lane] - g_mu[lane] * a0;
    float a1 = g_rstd[lane + 32] * g1[lane + 32];
    float bb1 = b1[lane + 32] - g_mu[lane + 32] * a1;
    int st = g_rowptr[d], en = g_rowptr[d + 1];
    float acc0 = 0.f, acc1 = 0.f;
    for (int p0 = st; p0 < en; p0 += 32) {
        int pp = p0 + lane;
        int sreg = (pp < en) ? g_srcs[pp] : 0;
        int cnt = min(32, en - p0);
        for (int j = 0; j < cnt; j++) {
            int s = __shfl_sync(0xffffffff, sreg, j);
            float v0 = g_h1raw[(size_t)s * 64 + lane];
            float v1 = g_h1raw[(size_t)s * 64 + lane + 32];
            acc0 += fmaxf(0.f, v0 * a0 + bb0);
            acc1 += fmaxf(0.f, v1 * a1 + bb1);
        }
    }
    float inv = 1.f / fmaxf((float)(en - st), 1.f);
    float sv0 = fmaxf(0.f, g_h1raw[(size_t)d * 64 + lane] * a0 + bb0);
    float sv1 = fmaxf(0.f, g_h1raw[(size_t)d * 64 + lane + 32] * a1 + bb1);
    size_t o = (size_t)d * 128;
    g_cat2[o + lane] = acc0 * inv;
    g_cat2[o + lane + 32] = acc1 * inv;
    g_cat2[o + 64 + lane] = sv0;
    g_cat2[o + 96 + lane] = sv1;
}

// ---------------- tf32 GEMM with fused BN stats epilogue ----------------
__device__ __forceinline__ unsigned f2tf(float f) {
    unsigned u;
    asm("cvt.rna.tf32.f32 %0, %1;" : "=r"(u) : "f"(f));
    return u;
}

#define CP16(saddr, gptr) \
    asm volatile("cp.async.cg.shared.global [%0], [%1], 16;" :: "r"(saddr), "l"(gptr))
#define CP_COMMIT() asm volatile("cp.async.commit_group;" ::: "memory")
#define CP_WAIT1() asm volatile("cp.async.wait_group 1;" ::: "memory")

// C = A[M,K] @ B[K,N]; grid (N/128, 128); per-block 128 rows; BN stats fused.
__global__ __launch_bounds__(256) void gemm_tf32(
    const float* __restrict__ A, int lda,
    const float* __restrict__ B, int ldb,
    float* __restrict__ C, int ldc, int K, int N) {
    __shared__ float As[2][128][20];
    __shared__ float Bs[2][16][136];
    __shared__ float ssum[128], ssq[128];
    int tid = threadIdx.x;
    int bm = blockIdx.y * 128, bn = blockIdx.x * 128;
    int w = tid >> 5, lane = tid & 31;
    int wm = (w & 3) * 32, wn = (w >> 2) * 64;
    int g = lane >> 2, tg = lane & 3;

    float acc[2][8][4];
#pragma unroll
    for (int mi = 0; mi < 2; mi++)
#pragma unroll
        for (int ni = 0; ni < 8; ni++)
#pragma unroll
            for (int q = 0; q < 4; q++) acc[mi][ni][q] = 0.f;

    int arow = tid >> 2, ac4 = (tid & 3) * 4;
    int bkr = tid >> 5, bc4 = lane * 4;
    const float* apA = A + (size_t)(bm + arow) * lda + ac4;
    const float* apB = A + (size_t)(bm + arow + 64) * lda + ac4;
    const float* bpA = B + (size_t)bkr * ldb + bn + bc4;
    const float* bpB = B + (size_t)(bkr + 8) * ldb + bn + bc4;
    unsigned sA0 = (unsigned)__cvta_generic_to_shared(&As[0][arow][ac4]);
    unsigned sA1 = (unsigned)__cvta_generic_to_shared(&As[0][arow + 64][ac4]);
    unsigned sB0 = (unsigned)__cvta_generic_to_shared(&Bs[0][bkr][bc4]);
    unsigned sB1 = (unsigned)__cvta_generic_to_shared(&Bs[0][bkr + 8][bc4]);
    const unsigned stA = 128 * 20 * 4, stB = 16 * 136 * 4;
    int T = K >> 4;

#define PREFETCH(t, st_) do { \
    CP16(sA0 + (st_) * stA, apA + (t) * 16); \
    CP16(sA1 + (st_) * stA, apB + (t) * 16); \
    CP16(sB0 + (st_) * stB, bpA + (size_t)(t) * 16 * ldb); \
    CP16(sB1 + (st_) * stB, bpB + (size_t)(t) * 16 * ldb); } while (0)

    PREFETCH(0, 0);
    CP_COMMIT();
    if (T > 1) PREFETCH(1, 1);
    CP_COMMIT();

    for (int i = 0; i < T; i++) {
        CP_WAIT1();
        __syncthreads();
        int s = i & 1;
#pragma unroll
        for (int ks = 0; ks < 2; ks++) {
            int k0 = ks * 8;
            unsigned a[2][4], b[8][2];
#pragma unroll
            for (int mi = 0; mi < 2; mi++) {
                int r = wm + mi * 16;
                a[mi][0] = f2tf(As[s][r + g][k0 + tg]);
                a[mi][1] = f2tf(As[s][r + g + 8][k0 + tg]);
                a[mi][2] = f2tf(As[s][r + g][k0 + tg + 4]);
                a[mi][3] = f2tf(As[s][r + g + 8][k0 + tg + 4]);
            }
#pragma unroll
            for (int ni = 0; ni < 8; ni++) {
                b[ni][0] = f2tf(Bs[s][k0 + tg][wn + ni * 8 + g]);
                b[ni][1] = f2tf(Bs[s][k0 + tg + 4][wn + ni * 8 + g]);
            }
#pragma unroll
            for (int mi = 0; mi < 2; mi++)
#pragma unroll
                for (int ni = 0; ni < 8; ni++)
                    asm volatile(
                        "mma.sync.aligned.m16n8k8.row.col.f32.tf32.tf32.f32 "
                        "{%0,%1,%2,%3}, {%4,%5,%6,%7}, {%8,%9}, {%0,%1,%2,%3};"
                        : "+f"(acc[mi][ni][0]), "+f"(acc[mi][ni][1]),
                          "+f"(acc[mi][ni][2]), "+f"(acc[mi][ni][3])
                        : "r"(a[mi][0]), "r"(a[mi][1]), "r"(a[mi][2]), "r"(a[mi][3]),
                          "r"(b[ni][0]), "r"(b[ni][1]));
        }
        __syncthreads();
        if (i + 2 < T) PREFETCH(i + 2, s);
        CP_COMMIT();
    }

    // store C + per-thread column partials (sum, sumsq over this thread's 4 rows/col)
    float cs0[8], cs1[8], cq0[8], cq1[8];
#pragma unroll
    for (int ni = 0; ni < 8; ni++) { cs0[ni] = cs1[ni] = cq0[ni] = cq1[ni] = 0.f; }
#pragma unroll
    for (int mi = 0; mi < 2; mi++) {
#pragma unroll
        for (int ni = 0; ni < 8; ni++) {
            int row = bm + wm + mi * 16 + g;
            int col = bn + wn + ni * 8 + 2 * tg;
            float v0 = acc[mi][ni][0], v1 = acc[mi][ni][1];
            float v2 = acc[mi][ni][2], v3 = acc[mi][ni][3];
            *reinterpret_cast<float2*>(C + (size_t)row * ldc + col) = make_float2(v0, v1);
            *reinterpret_cast<float2*>(C + (size_t)(row + 8) * ldc + col) = make_float2(v2, v3);
            cs0[ni] += v0 + v2; cq0[ni] += v0 * v0 + v2 * v2;
            cs1[ni] += v1 + v3; cq1[ni] += v1 * v1 + v3 * v3;
        }
    }
    // reduce over g (lanes stride 4): results land in lanes 0..3 (tg)
#pragma unroll
    for (int off = 16; off >= 4; off >>= 1) {
#pragma unroll
        for (int ni = 0; ni < 8; ni++) {
            cs0[ni] += __shfl_down_sync(0xffffffff, cs0[ni], off);
            cs1[ni] += __shfl_down_sync(0xffffffff, cs1[ni], off);
            cq0[ni] += __shfl_down_sync(0xffffffff, cq0[ni], off);
            cq1[ni] += __shfl_down_sync(0xffffffff, cq1[ni], off);
        }
    }
    // fixed-warp-order accumulation into smem (deterministic)
    for (int w4 = 0; w4 < 4; w4++) {
        if ((w & 3) == w4 && lane < 4) {
#pragma unroll
            for (int ni = 0; ni < 8; ni++) {
                int cl = wn + ni * 8 + 2 * lane;
                if (w4 == 0) {
                    ssum[cl] = cs0[ni]; ssq[cl] = cq0[ni];
                    ssum[cl + 1] = cs1[ni]; ssq[cl + 1] = cq1[ni];
                } else {
                    ssum[cl] += cs0[ni]; ssq[cl] += cq0[ni];
                    ssum[cl + 1] += cs1[ni]; ssq[cl + 1] += cq1[ni];
                }
            }
        }
        __syncthreads();
    }
    if (tid < 128) {
        g_bnps[blockIdx.y * 512 + bn + tid] = ssum[tid];
        g_bnpq[blockIdx.y * 512 + bn + tid] = ssq[tid];
    }
    bn_finalize_tail(N, N, tid);   // grid has N blocks total
#undef PREFETCH
}

// ---------------- GAT ----------------
__global__ void vsd_kernel(const float* __restrict__ W, const float* __restrict__ asrc,
                           const float* __restrict__ adst) {
    int wid = (blockIdx.x * 256 + threadIdx.x) >> 5;  // 0..511
    int lane = threadIdx.x & 31;
    int h = wid >> 7, k = wid & 127;
    const float* wr = W + (size_t)k * 1024 + h * 256;
    const float* as = asrc + h * 256;
    const float* ad = adst + h * 256;
    float a = 0, b = 0;
    for (int j = lane; j < 256; j += 32) { float wv = wr[j]; a += wv * as[j]; b += wv * ad[j]; }
#pragma unroll
    for (int off = 16; off > 0; off >>= 1) {
        a += __shfl_down_sync(0xffffffff, a, off);
        b += __shfl_down_sync(0xffffffff, b, off);
    }
    if (lane == 0) { g_vsrc[wid] = a; g_vdst[wid] = b; }
}

// BN2 apply + relu -> h2, AND per-row es/ed dots. block=256 -> 2 rows.
__global__ void bn2_apply_esed(const float* __restrict__ g2, const float* __restrict__ b2) {
    __shared__ float red[2][8][4];
    int tid = threadIdx.x;
    int lr = tid >> 7;
    int c = tid & 127;
    int row = blockIdx.x * 2 + lr;
    float a = g_rstd[c] * g2[c], bb = b2[c] - g_mu[c] * a;
    float v = fmaxf(0.f, g_h2raw[(size_t)row * 128 + c] * a + bb);
    g_h2[(size_t)row * 128 + c] = v;
    float pr[8];
#pragma unroll
    for (int h = 0; h < 4; h++) {
        pr[h] = v * g_vsrc[h * 128 + c];
        pr[4 + h] = v * g_vdst[h * 128 + c];
    }
#pragma unroll
    for (int off = 16; off > 0; off >>= 1)
#pragma unroll
        for (int i = 0; i < 8; i++) pr[i] += __shfl_down_sync(0xffffffff, pr[i], off);
    int wr = (tid >> 5) & 3;
    if ((tid & 31) == 0)
#pragma unroll
        for (int i = 0; i < 8; i++) red[lr][i][wr] = pr[i];
    __syncthreads();
    if (tid < 16) {
        int r2 = tid >> 3, qi = tid & 7;
        float s = red[r2][qi][0] + red[r2][qi][1] + red[r2][qi][2] + red[r2][qi][3];
        int rr = blockIdx.x * 2 + r2;
        if (qi < 4) g_es[rr * 4 + qi] = s;
        else g_ed[rr * 4 + qi - 4] = s;
    }
}

__device__ __forceinline__ float lrelu(float x) { return x > 0.f ? x : 0.2f * x; }

// online softmax stats per (dst, 4 heads); warp per dst, deterministic shuffle tree
__global__ void gat_mz_kernel() {
    int lane = threadIdx.x & 31;
    int d = blockIdx.x * 8 + (threadIdx.x >> 5);
    float4 ed4 = *reinterpret_cast<const float4*>(g_ed + d * 4);
    float4 es4 = *reinterpret_cast<const float4*>(g_es + d * 4);
    float edv[4] = {ed4.x, ed4.y, ed4.z, ed4.w};
    float selfe[4] = {lrelu(es4.x + edv[0]), lrelu(es4.y + edv[1]),
                      lrelu(es4.z + edv[2]), lrelu(es4.w + edv[3])};
    float m[4], z[4];
#pragma unroll
    for (int h = 0; h < 4; h++) {
        m[h] = (lane == 0) ? selfe[h] : -1e30f;
        z[h] = (lane == 0) ? 1.f : 0.f;
    }
    int st = g_rowptr[d], en = g_rowptr[d + 1];
    for (int p = st + lane; p < en; p += 32) {
        int s = g_srcs[p];
        float4 e4 = *reinterpret_cast<const float4*>(g_es + s * 4);
        float ee[4] = {lrelu(e4.x + edv[0]), lrelu(e4.y + edv[1]),
                       lrelu(e4.z + edv[2]), lrelu(e4.w + edv[3])};
#pragma unroll
        for (int h = 0; h < 4; h++) {
            float nm = fmaxf(m[h], ee[h]);
            z[h] = z[h] * expf(m[h] - nm) + expf(ee[h] - nm);
            m[h] = nm;
        }
    }
#pragma unroll
    for (int off = 16; off > 0; off >>= 1) {
#pragma unroll
        for (int h = 0; h < 4; h++) {
            float om = __shfl_down_sync(0xffffffff, m[h], off);
            float oz = __shfl_down_sync(0xffffffff, z[h], off);
            float nm = fmaxf(m[h], om);
            z[h] = z[h] * expf(m[h] - nm) + oz * expf(om - nm);
            m[h] = nm;
        }
    }
    if (lane == 0) {
#pragma unroll
        for (int h = 0; h < 4; h++) {
            float zi = 1.f / z[h];
            g_mh[d * 4 + h] = m[h];
            g_zi[d * 4 + h] = zi;
            g_aself[d * 4 + h] = expf(selfe[h] - m[h]) * zi;
        }
    }
}

// weighted gather with inline alpha; warp per dst, 4 ch/lane x 4 heads
__global__ void gat_gather_kernel(const float* __restrict__ h2) {
    int lane = threadIdx.x & 31;
    int d = blockIdx.x * 8 + (threadIdx.x >> 5);
    float4 ed4 = *reinterpret_cast<const float4*>(g_ed + d * 4);
    float4 mh4 = *reinterpret_cast<const float4*>(g_mh + d * 4);
    float4 zi4 = *reinterpret_cast<const float4*>(g_zi + d * 4);
    float edv[4] = {ed4.x, ed4.y, ed4.z, ed4.w};
    float mh[4] = {mh4.x, mh4.y, mh4.z, mh4.w};
    float zi[4] = {zi4.x, zi4.y, zi4.z, zi4.w};
    float4 as4 = *reinterpret_cast<const float4*>(g_aself + d * 4);
    float asf[4] = {as4.x, as4.y, as4.z, as4.w};
    float hv[4], acc[4][4];
#pragma unroll
    for (int k = 0; k < 4; k++) {
        hv[k] = h2[(size_t)d * 128 + lane + k * 32];
#pragma unroll
        for (int h = 0; h < 4; h++) acc[h][k] = asf[h] * hv[k];
    }
    int st = g_rowptr[d], en = g_rowptr[d + 1];
    for (int p0 = st; p0 < en; p0 += 32) {
        int pp = p0 + lane;
        int sreg = 0;
        float al[4] = {0.f, 0.f, 0.f, 0.f};
        if (pp < en) {
            sreg = g_srcs[pp];
            float4 e4 = *reinterpret_cast<const float4*>(g_es + sreg * 4);
            al[0] = expf(lrelu(e4.x + edv[0]) - mh[0]) * zi[0];
            al[1] = expf(lrelu(e4.y + edv[1]) - mh[1]) * zi[1];
            al[2] = expf(lrelu(e4.z + edv[2]) - mh[2]) * zi[2];
            al[3] = expf(lrelu(e4.w + edv[3]) - mh[3]) * zi[3];
        }
        int cnt = min(32, en - p0);
        for (int j = 0; j < cnt; j++) {
            int s = __shfl_sync(0xffffffff, sreg, j);
            float a0 = __shfl_sync(0xffffffff, al[0], j);
            float a1 = __shfl_sync(0xffffffff, al[1], j);
            float a2 = __shfl_sync(0xffffffff, al[2], j);
            float a3 = __shfl_sync(0xffffffff, al[3], j);
#pragma unroll
            for (int k = 0; k < 4; k++) {
                float sv = h2[(size_t)s * 128 + lane + k * 32];
                acc[0][k] += a0 * sv; acc[1][k] += a1 * sv;
                acc[2][k] += a2 * sv; acc[3][k] += a3 * sv;
            }
        }
    }
#pragma unroll
    for (int h = 0; h < 4; h++)
#pragma unroll
        for (int k = 0; k < 4; k++)
            g_gatagg[(size_t)d * 512 + h * 128 + lane + k * 32] = acc[h][k];
}

// ---------------- layer 4: GCN agg with BN3+relu fused; warp per dst ----------------
__global__ void agg_gcn4_kernel(const float* __restrict__ bg, const float* __restrict__ bb) {
    int lane = threadIdx.x & 31;
    int d = blockIdx.x * 8 + (threadIdx.x >> 5);
    float a[8], b2[8];
#pragma unroll
    for (int k = 0; k < 8; k++) {
        int c = lane + k * 32;
        a[k] = g_rstd[c] * bg[c];
        b2[k] = bb[c] - g_mu[c] * a[k];
    }
    float dd = g_dis[d];
    float acc[8];
#pragma unroll
    for (int k = 0; k < 8; k++) {
        float v = g_h3raw[(size_t)d * 256 + lane + k * 32];
        acc[k] = dd * dd * fmaxf(0.f, v * a[k] + b2[k]);
    }
    int st = g_rowptr[d], en = g_rowptr[d + 1];
    for (int p0 = st; p0 < en; p0 += 32) {
        int pp = p0 + lane;
        int sreg = 0;
        float wreg = 0.f;
        if (pp < en) { sreg = g_srcs[pp]; wreg = g_dis[sreg] * dd; }
        int cnt = min(32, en - p0);
        for (int j = 0; j < cnt; j++) {
            int s = __shfl_sync(0xffffffff, sreg, j);
            float w = __shfl_sync(0xffffffff, wreg, j);
#pragma unroll
            for (int k = 0; k < 8; k++) {
                float v = g_h3raw[(size_t)s * 256 + lane + k * 32];
                acc[k] += w * fmaxf(0.f, v * a[k] + b2[k]);
            }
        }
    }
#pragma unroll
    for (int k = 0; k < 8; k++)
        g_gcn4agg[(size_t)d * 256 + lane + k * 32] = acc[k];
}

// ---------------- pooling (BN4+relu fused) + FC ----------------
__global__ void pool_kernel(const float* __restrict__ g4, const float* __restrict__ b4) {
    int g = blockIdx.x, c = threadIdx.x;  // 32 blocks x 512 threads
    float a = g_rstd[c] * g4[c];
    float b2 = b4[c] - g_mu[c] * a;
    int start = 0;
    for (int i = 0; i < g; i++) start += g_gcnt[i];
    int cnt = g_gcnt[g];
    float s = 0.f, mx = -3.402823e38f;
    for (int r = start; r < start + cnt; r++) {
        float v = fmaxf(0.f, g_h4raw[(size_t)r * 512 + c] * a + b2);
        s += v;
        mx = fmaxf(mx, v);
    }
    g_pooled[g * 1024 + c] = s / fmaxf((float)cnt, 1.f);
    g_pooled[g * 1024 + 512 + c] = (cnt > 0) ? mx : 0.f;
}

__global__ void fc_kernel(const float* __restrict__ w, const float* __restrict__ bias,
                          float* __restrict__ out) {
    __shared__ float pt[32 * 128];
    int jb = blockIdx.x * 16;              // 64 blocks x 16 cols
    int j = jb + (threadIdx.x & 15);
    int gq = threadIdx.x >> 4;             // 0..15, 2 graphs each
    float acc[2] = {0.f, 0.f};
    for (int kt = 0; kt < 1024; kt += 128) {
        __syncthreads();
        for (int i = threadIdx.x; i < 4096; i += 256) {
            int g = i >> 7, kk = i & 127;
            pt[g * 128 + kk] = g_pooled[g * 1024 + kt + kk];
        }
        __syncthreads();
        for (int kk = 0; kk < 128; kk++) {
            float wv = w[(size_t)(kt + kk) * 1024 + j];
            acc[0] += pt[(gq * 2) * 128 + kk] * wv;
            acc[1] += pt[(gq * 2 + 1) * 128 + kk] * wv;
        }
    }
    out[(gq * 2) * 1024 + j] = acc[0] + bias[j];
    out[(gq * 2 + 1) * 1024 + j] = acc[1] + bias[j];
}

// ---------------- driver ----------------
extern "C" void kernel_launch(void* const* d_in, const int* in_sizes, int n_in,
                              void* d_out, int out_size) {
    const float* x        = (const float*)d_in[0];
    const int*   eidx     = (const int*)d_in[1];
    const int*   batch    = (const int*)d_in[2];
    const float* gcn1_w   = (const float*)d_in[3];
    const float* sage_wl  = (const float*)d_in[5];
    const float* sage_wr  = (const float*)d_in[6];
    const float* gat_w    = (const float*)d_in[8];
    const float* gat_asrc = (const float*)d_in[9];
    const float* gat_adst = (const float*)d_in[10];
    const float* gcn4_w   = (const float*)d_in[12];
    const float* bn1_g = (const float*)d_in[14], *bn1_b = (const float*)d_in[15];
    const float* bn2_g = (const float*)d_in[16], *bn2_b = (const float*)d_in[17];
    const float* bn3_g = (const float*)d_in[18], *bn3_b = (const float*)d_in[19];
    const float* bn4_g = (const float*)d_in[20], *bn4_b = (const float*)d_in[21];
    const float* fc_w = (const float*)d_in[22], *fc_b = (const float*)d_in[23];
    const int* src = eidx;
    const int* dst = eidx + EE;
    float* out = (float*)d_out;

    float *agg0, *cat2, *h2raw, *h2, *gatagg, *h3raw, *gcn4agg, *h4raw, *Bsage, *Bgat;
    cudaGetSymbolAddress((void**)&agg0, g_agg0);
    cudaGetSymbolAddress((void**)&cat2, g_cat2);
    cudaGetSymbolAddress((void**)&h2raw, g_h2raw);
    cudaGetSymbolAddress((void**)&h2, g_h2);
    cudaGetSymbolAddress((void**)&gatagg, g_gatagg);
    cudaGetSymbolAddress((void**)&h3raw, g_h3raw);
    cudaGetSymbolAddress((void**)&gcn4agg, g_gcn4agg);
    cudaGetSymbolAddress((void**)&h4raw, g_h4raw);
    cudaGetSymbolAddress((void**)&Bsage, g_Bsage);
    cudaGetSymbolAddress((void**)&Bgat, g_Bgat);

    // preprocessing
    setup_kernel<<<512, 256>>>(sage_wl, sage_wr, gat_w);
    count_kernel<<<512, 256>>>(dst, batch);
    scan_kernel<<<1, 1024>>>();
    scatter_dis_kernel<<<512, 256>>>(src, dst);
    sort_kernel<<<NN / 8, 256>>>();

    // layer 1: GCN(5->64), stats fused
    agg5_kernel<<<64, 256>>>(x);
    gemm_k5_bn<<<128, 256>>>(agg0, gcn1_w);

    // layer 2: SAGE(64->128): BN1 fused into agg; one K=128 GEMM w/ stats
    agg_sage_bn1<<<NN / 8, 256>>>(bn1_g, bn1_b);
    gemm_tf32<<<dim3(1, 128), 256>>>(cat2, 128, Bsage, 128, h2raw, 128, 128, 128);

    // layer 3: GAT(128->256, 4 heads)
    vsd_kernel<<<64, 256>>>(gat_w, gat_asrc, gat_adst);
    bn2_apply_esed<<<NN / 2, 256>>>(bn2_g, bn2_b);
    gat_mz_kernel<<<NN / 8, 256>>>();
    gat_gather_kernel<<<NN / 8, 256>>>(h2);
    gemm_tf32<<<dim3(2, 128), 256>>>(gatagg, 512, Bgat, 256, h3raw, 256, 512, 256);

    // layer 4: GCN(256->512): BN3 fused into agg
    agg_gcn4_kernel<<<NN / 8, 256>>>(bn3_g, bn3_b);
    gemm_tf32<<<dim3(4, 128), 256>>>(gcn4agg, 256, gcn4_w, 512, h4raw, 512, 256, 512);

    // pooling (BN4 fused) + FC
    pool_kernel<<<GG, 512>>>(bn4_g, bn4_b);
    fc_kernel<<<64, 256>>>(fc_w, fc_b, out);
}